// round 3
// baseline (speedup 1.0000x reference)
#include <cuda_runtime.h>
#include <cuda_fp16.h>
#include <cstdint>
#include <cstddef>

// ---------------- problem constants ----------------
#define O_DIM 4096
#define I_DIM 4096
#define S_DIM 2048
#define M_TOT 8192            // B*S = 4*2048
#define GRP   128             // quant group size along K

// ---------------- GEMM tiling ----------------
#define BM 128
#define BN 128
#define BK 128                // int8 elements per stage = one scale group
#define STAGES 4
#define NKS (I_DIM / BK)      // 32 k-stages
#define A_STG (BM * BK)       // 16384 B
#define B_STG (BN * BK)       // 16384 B
#define STAGE_BYTES (A_STG + B_STG)          // 32768
#define SCALE_OFF (STAGES * STAGE_BYTES)     // 131072
#define SCALE_PITCH 129                      // padded floats per group row
#define SMEM_TOTAL (SCALE_OFF + 32 * SCALE_PITCH * 4)  // 147584

// magic-bias int->float exact conversion (|P| < 2^22)
#define MAGIC_I 0x4B400000
#define MAGIC_F 12582912.0f

// ---------------- device scratch ----------------
__device__ int8_t g_W8[(size_t)O_DIM * I_DIM];   // w_int - zero, int8 [O][I]
__device__ int8_t g_X8[(size_t)M_TOT * I_DIM];   // quantized activations [M][I]

// ---------------- asm helpers ----------------
__device__ __forceinline__ uint32_t smem_u32(const void* p) {
    uint32_t a;
    asm("{ .reg .u64 t; cvta.to.shared.u64 t, %1; cvt.u32.u64 %0, t; }" : "=r"(a) : "l"(p));
    return a;
}
#define CP_ASYNC16(saddr, gptr) \
    asm volatile("cp.async.cg.shared.global [%0], [%1], 16;" :: "r"(saddr), "l"(gptr) : "memory")
#define CP_COMMIT() asm volatile("cp.async.commit_group;" ::: "memory")
#define CP_WAIT2()  asm volatile("cp.async.wait_group 2;" ::: "memory")

#define LDSM_X4(r0, r1, r2, r3, addr)                                              \
    asm volatile("ldmatrix.sync.aligned.m8n8.x4.shared.b16 {%0,%1,%2,%3}, [%4];"   \
                 : "=r"(r0), "=r"(r1), "=r"(r2), "=r"(r3) : "r"(addr))

#define MMA_S8(c, a, b0_, b1_)                                                     \
    asm volatile("mma.sync.aligned.m16n8k32.row.col.s32.s8.s8.s32 "                \
                 "{%0,%1,%2,%3}, {%4,%5,%6,%7}, {%8,%9}, {%0,%1,%2,%3};"           \
                 : "+r"((c)[0]), "+r"((c)[1]), "+r"((c)[2]), "+r"((c)[3])          \
                 : "r"((a)[0]), "r"((a)[1]), "r"((a)[2]), "r"((a)[3]),             \
                   "r"(b0_), "r"(b1_))

// ---------------- kernel 1: fused prep (wpack + quant) ----------------
// blocks [0, WB): pack weights to int8 (w_int - zero)
// blocks [WB, WB+QB): quantize activations to int8
#define WB (O_DIM * 2048 / 4 / 256)                    // 8192
#define QB ((int)((size_t)M_TOT * I_DIM / 8 / 256))    // 16384

__global__ void prep_kernel(const int* __restrict__ qw, const int* __restrict__ wz,
                            const float* __restrict__ x, const float* __restrict__ as_) {
    if (blockIdx.x < WB) {
        int t = blockIdx.x * blockDim.x + threadIdx.x;
        int o = t >> 9;
        int j = (t & 511) * 4;              // int32 index within row
        int g = j >> 6;                     // group = (2j)/128
        int z = __ldg(&wz[o * 32 + g]);
        int4 q = *reinterpret_cast<const int4*>(qw + (size_t)o * 2048 + j);
        int qs[4] = {q.x, q.y, q.z, q.w};
        uint32_t lo = 0, hi = 0;
#pragma unroll
        for (int r = 0; r < 2; r++) {
            lo |= (uint32_t)(uint8_t)((qs[r] & 15) - z) << (r * 16);
            lo |= (uint32_t)(uint8_t)(((qs[r] >> 4) & 15) - z) << (r * 16 + 8);
            hi |= (uint32_t)(uint8_t)((qs[r + 2] & 15) - z) << (r * 16);
            hi |= (uint32_t)(uint8_t)(((qs[r + 2] >> 4) & 15) - z) << (r * 16 + 8);
        }
        uint2 outv; outv.x = lo; outv.y = hi;
        *reinterpret_cast<uint2*>(&g_W8[(size_t)o * I_DIM + j * 2]) = outv;
    } else {
        int t = (blockIdx.x - WB) * blockDim.x + threadIdx.x;
        size_t e8 = (size_t)t * 8;
        int m = (int)(e8 >> 12);
        float s = __ldg(&as_[m & (S_DIM - 1)]);
        float4 v0 = *reinterpret_cast<const float4*>(x + e8);
        float4 v1 = *reinterpret_cast<const float4*>(x + e8 + 4);
        float vv[8] = {v0.x, v0.y, v0.z, v0.w, v1.x, v1.y, v1.z, v1.w};
        uint32_t lo = 0, hi = 0;
#pragma unroll
        for (int i = 0; i < 4; i++) {
            int n = (int)rintf(vv[i] / s);
            n = max(-127, min(127, n));
            lo |= ((uint32_t)(uint8_t)(int8_t)n) << (i * 8);
        }
#pragma unroll
        for (int i = 0; i < 4; i++) {
            int n = (int)rintf(vv[4 + i] / s);
            n = max(-127, min(127, n));
            hi |= ((uint32_t)(uint8_t)(int8_t)n) << (i * 8);
        }
        uint2 outv; outv.x = lo; outv.y = hi;
        *reinterpret_cast<uint2*>(&g_X8[e8]) = outv;
    }
}

// ---------------- kernel 2: int8 GEMM with magic-bias group promotion ----------------
__global__ void __launch_bounds__(512, 1)
gemm_kernel(const float* __restrict__ ws,         // weight_scale [O][32]
            const float* __restrict__ act_scale,  // [2048]
            const float* __restrict__ bias,       // [4096]
            float* __restrict__ out) {            // [M][O]
    extern __shared__ char smem[];
    const uint32_t sbase = smem_u32(smem);
    float* sscale = reinterpret_cast<float*>(smem + SCALE_OFF);

    const int tid  = threadIdx.x;
    const int lane = tid & 31;
    const int wid  = tid >> 5;
    const int wm   = wid & 3;       // 4 warps along M
    const int wn   = wid >> 2;      // 4 warps along N
    const int n0   = blockIdx.x * BN;
    const int m0   = blockIdx.y * BM;

    // ---- preload per-column group scales: sscale[g*129 + nl] = ws[(n0+nl)*32+g]
#pragma unroll 2
    for (int i = tid; i < BN * 32; i += 512) {
        int nl = i >> 5, g = i & 31;
        sscale[g * SCALE_PITCH + nl] = __ldg(&ws[(size_t)(n0 + nl) * 32 + g]);
    }

    // ---- per-thread ldmatrix address precompute
    const int mi = lane >> 3;          // matrix index 0..3
    const int rr = lane & 7;
    const int c0 = mi >> 1;            // k-half chunk offset
    const int roff = (mi & 1) * 8;
    int rowA[2], rowB[2];
#pragma unroll
    for (int mb = 0; mb < 2; mb++) rowA[mb] = wm * 32 + mb * 16 + roff + rr;
#pragma unroll
    for (int nb = 0; nb < 2; nb++) rowB[nb] = wn * 32 + nb * 16 + roff + rr;

    // ---- accumulators (int accum seeded with magic bias)
    int   ai[2][4][4];
    float af[2][4][4];
#pragma unroll
    for (int mb = 0; mb < 2; mb++)
#pragma unroll
        for (int bb = 0; bb < 4; bb++)
#pragma unroll
            for (int r = 0; r < 4; r++) { ai[mb][bb][r] = MAGIC_I; af[mb][bb][r] = 0.f; }

    // ---- stage loader (cp.async, XOR-swizzled 16B chunks)
    auto load_stage = [&](int ks, int slot) {
        const uint32_t sA = sbase + slot * STAGE_BYTES;
        const uint32_t sB = sA + A_STG;
        const int8_t* gA = g_X8 + (size_t)m0 * I_DIM + ks * BK;
        const int8_t* gB = g_W8 + (size_t)n0 * I_DIM + ks * BK;
#pragma unroll
        for (int i = 0; i < 2; i++) {
            int idx = tid + i * 512;
            int row = idx >> 3, ch = idx & 7;
            uint32_t sw = (uint32_t)(row * 128 + ((ch ^ (row & 7)) << 4));
            CP_ASYNC16(sA + sw, gA + (size_t)row * I_DIM + ch * 16);
            CP_ASYNC16(sB + sw, gB + (size_t)row * I_DIM + ch * 16);
        }
    };

    // ---- prologue: fill 3 of 4 stages
    for (int s = 0; s < STAGES - 1; s++) { load_stage(s, s); CP_COMMIT(); }

    const int q2 = (lane & 3) * 2;

    for (int ks = 0; ks < NKS; ks++) {
        CP_WAIT2();
        __syncthreads();
        // issue next stage into the slot freed last iteration
        const int pre = ks + STAGES - 1;
        if (pre < NKS) load_stage(pre, pre & (STAGES - 1));
        CP_COMMIT();

        const uint32_t sA = sbase + (ks & (STAGES - 1)) * STAGE_BYTES;
        const uint32_t sB = sA + A_STG;

#pragma unroll
        for (int kk = 0; kk < 4; kk++) {
            uint32_t a[2][4], br[2][4];
#pragma unroll
            for (int mb = 0; mb < 2; mb++) {
                int row = rowA[mb];
                uint32_t ad = sA + row * 128 + (((((uint32_t)kk << 1) | c0) ^ (row & 7)) << 4);
                LDSM_X4(a[mb][0], a[mb][1], a[mb][2], a[mb][3], ad);
            }
#pragma unroll
            for (int nb = 0; nb < 2; nb++) {
                int row = rowB[nb];
                uint32_t bd = sB + row * 128 + (((((uint32_t)kk << 1) | c0) ^ (row & 7)) << 4);
                LDSM_X4(br[nb][0], br[nb][1], br[nb][2], br[nb][3], bd);
            }
#pragma unroll
            for (int mb = 0; mb < 2; mb++) {
#pragma unroll
                for (int bb = 0; bb < 4; bb++) {
                    const int nb = bb >> 1, e = bb & 1;
                    MMA_S8(ai[mb][bb], a[mb], br[nb][e], br[nb][2 + e]);
                }
            }
        }

        // ---- promote this group's sums into float accumulators (exact, no I2F)
        // ai holds MAGIC + P; __int_as_float(ai) - MAGIC_F == (float)P exactly.
#pragma unroll
        for (int bb = 0; bb < 4; bb++) {
            const int nl = wn * 32 + bb * 8 + q2;
            const float s0 = sscale[ks * SCALE_PITCH + nl];
            const float s1 = sscale[ks * SCALE_PITCH + nl + 1];
#pragma unroll
            for (int mb = 0; mb < 2; mb++) {
                af[mb][bb][0] = __fmaf_rn(s0, __int_as_float(ai[mb][bb][0]) - MAGIC_F, af[mb][bb][0]);
                af[mb][bb][1] = __fmaf_rn(s1, __int_as_float(ai[mb][bb][1]) - MAGIC_F, af[mb][bb][1]);
                af[mb][bb][2] = __fmaf_rn(s0, __int_as_float(ai[mb][bb][2]) - MAGIC_F, af[mb][bb][2]);
                af[mb][bb][3] = __fmaf_rn(s1, __int_as_float(ai[mb][bb][3]) - MAGIC_F, af[mb][bb][3]);
                ai[mb][bb][0] = MAGIC_I; ai[mb][bb][1] = MAGIC_I;
                ai[mb][bb][2] = MAGIC_I; ai[mb][bb][3] = MAGIC_I;
            }
        }
    }

    // ---- epilogue: out = af * act_scale[m] + bias[n]
#pragma unroll
    for (int mb = 0; mb < 2; mb++) {
        const int r0 = m0 + wm * 32 + mb * 16 + (lane >> 2);
        const int r1 = r0 + 8;
        const float sa0 = __ldg(&act_scale[r0 & (S_DIM - 1)]);
        const float sa1 = __ldg(&act_scale[r1 & (S_DIM - 1)]);
#pragma unroll
        for (int bb = 0; bb < 4; bb++) {
            const int n = n0 + wn * 32 + bb * 8 + q2;
            const float2 bv = *reinterpret_cast<const float2*>(bias + n);
            float2 o0, o1;
            o0.x = af[mb][bb][0] * sa0 + bv.x;
            o0.y = af[mb][bb][1] * sa0 + bv.y;
            o1.x = af[mb][bb][2] * sa1 + bv.x;
            o1.y = af[mb][bb][3] * sa1 + bv.y;
            *reinterpret_cast<float2*>(out + (size_t)r0 * O_DIM + n) = o0;
            *reinterpret_cast<float2*>(out + (size_t)r1 * O_DIM + n) = o1;
        }
    }
}

// ---------------- host launcher ----------------
extern "C" void kernel_launch(void* const* d_in, const int* in_sizes, int n_in,
                              void* d_out, int out_size) {
    const float* x    = (const float*)d_in[0];
    const int*   qw   = (const int*)d_in[1];
    const float* as_  = (const float*)d_in[2];
    const float* ws   = (const float*)d_in[3];
    const int*   wz   = (const int*)d_in[4];
    const float* bias = (const float*)d_in[5];
    float* out = (float*)d_out;

    prep_kernel<<<WB + QB, 256>>>(qw, wz, x, as_);

    cudaFuncSetAttribute(gemm_kernel, cudaFuncAttributeMaxDynamicSharedMemorySize,
                         SMEM_TOTAL);
    gemm_kernel<<<dim3(O_DIM / BN, M_TOT / BM), 512, SMEM_TOTAL>>>(ws, as_, bias, out);
}

// round 6
// speedup vs baseline: 1.0154x; 1.0154x over previous
#include <cuda_runtime.h>
#include <cuda_fp16.h>
#include <cstdint>
#include <cstddef>

// ---------------- problem constants ----------------
#define O_DIM 4096
#define I_DIM 4096
#define S_DIM 2048
#define M_TOT 8192            // B*S = 4*2048

// ---------------- GEMM tiling ----------------
#define BM 128
#define BN 64
#define BK 128                // int8 elements per stage = one scale group
#define STAGES 4
#define NKS (I_DIM / BK)      // 32 k-stages
#define A_STG (BM * BK)       // 16384 B
#define B_STG (BN * BK)       // 8192 B
#define STAGE_BYTES (A_STG + B_STG)          // 24576
#define SCALE_OFF (STAGES * STAGE_BYTES)     // 98304
#define SCALE_PITCH 65                       // padded floats per group row (BN=64)
#define SMEM_TOTAL (SCALE_OFF + 32 * SCALE_PITCH * 4)  // 106624  (x2 CTAs fits 228KB/SM)

// magic-bias int->float exact conversion (|P| < 2^22)
#define MAGIC_I 0x4B400000
#define MAGIC_F 12582912.0f

// ---------------- device scratch ----------------
__device__ int8_t g_W8[(size_t)O_DIM * I_DIM];   // w_int - zero, int8 [O][I]
__device__ int8_t g_X8[(size_t)M_TOT * I_DIM];   // quantized activations [M][I]

// ---------------- asm helpers ----------------
__device__ __forceinline__ uint32_t smem_u32(const void* p) {
    uint32_t a;
    asm("{ .reg .u64 t; cvta.to.shared.u64 t, %1; cvt.u32.u64 %0, t; }" : "=r"(a) : "l"(p));
    return a;
}
#define CP_ASYNC16(saddr, gptr) \
    asm volatile("cp.async.cg.shared.global [%0], [%1], 16;" :: "r"(saddr), "l"(gptr) : "memory")
#define CP_COMMIT() asm volatile("cp.async.commit_group;" ::: "memory")
#define CP_WAIT2()  asm volatile("cp.async.wait_group 2;" ::: "memory")

#define LDSM_X4(r0, r1, r2, r3, addr)                                              \
    asm volatile("ldmatrix.sync.aligned.m8n8.x4.shared.b16 {%0,%1,%2,%3}, [%4];"   \
                 : "=r"(r0), "=r"(r1), "=r"(r2), "=r"(r3) : "r"(addr))

#define MMA_S8(c, a, b0_, b1_)                                                     \
    asm volatile("mma.sync.aligned.m16n8k32.row.col.s32.s8.s8.s32 "                \
                 "{%0,%1,%2,%3}, {%4,%5,%6,%7}, {%8,%9}, {%0,%1,%2,%3};"           \
                 : "+r"((c)[0]), "+r"((c)[1]), "+r"((c)[2]), "+r"((c)[3])          \
                 : "r"((a)[0]), "r"((a)[1]), "r"((a)[2]), "r"((a)[3]),             \
                   "r"(b0_), "r"(b1_))

// ---------------- kernel 1: fused prep (wpack + quant) ----------------
#define WB (O_DIM * 2048 / 4 / 256)                    // 8192 blocks: weight pack
#define QB ((int)((size_t)M_TOT * I_DIM / 8 / 256))    // 16384 blocks: activation quant

__global__ void prep_kernel(const int* __restrict__ qw, const int* __restrict__ wz,
                            const float* __restrict__ x, const float* __restrict__ as_) {
    if (blockIdx.x < WB) {
        int t = blockIdx.x * blockDim.x + threadIdx.x;
        int o = t >> 9;
        int j = (t & 511) * 4;              // int32 index within row
        int g = j >> 6;                     // group = (2j)/128
        int z = __ldg(&wz[o * 32 + g]);
        int4 q = *reinterpret_cast<const int4*>(qw + (size_t)o * 2048 + j);
        int qs[4] = {q.x, q.y, q.z, q.w};
        uint32_t lo = 0, hi = 0;
#pragma unroll
        for (int r = 0; r < 2; r++) {
            lo |= (uint32_t)(uint8_t)((qs[r] & 15) - z) << (r * 16);
            lo |= (uint32_t)(uint8_t)(((qs[r] >> 4) & 15) - z) << (r * 16 + 8);
            hi |= (uint32_t)(uint8_t)((qs[r + 2] & 15) - z) << (r * 16);
            hi |= (uint32_t)(uint8_t)(((qs[r + 2] >> 4) & 15) - z) << (r * 16 + 8);
        }
        uint2 outv; outv.x = lo; outv.y = hi;
        *reinterpret_cast<uint2*>(&g_W8[(size_t)o * I_DIM + j * 2]) = outv;
    } else {
        int t = (blockIdx.x - WB) * blockDim.x + threadIdx.x;
        size_t e8 = (size_t)t * 8;
        int m = (int)(e8 >> 12);
        float s = __ldg(&as_[m & (S_DIM - 1)]);
        float4 v0 = *reinterpret_cast<const float4*>(x + e8);
        float4 v1 = *reinterpret_cast<const float4*>(x + e8 + 4);
        float vv[8] = {v0.x, v0.y, v0.z, v0.w, v1.x, v1.y, v1.z, v1.w};
        uint32_t lo = 0, hi = 0;
#pragma unroll
        for (int i = 0; i < 4; i++) {
            int n = (int)rintf(vv[i] / s);
            n = max(-127, min(127, n));
            lo |= ((uint32_t)(uint8_t)(int8_t)n) << (i * 8);
        }
#pragma unroll
        for (int i = 0; i < 4; i++) {
            int n = (int)rintf(vv[4 + i] / s);
            n = max(-127, min(127, n));
            hi |= ((uint32_t)(uint8_t)(int8_t)n) << (i * 8);
        }
        uint2 outv; outv.x = lo; outv.y = hi;
        *reinterpret_cast<uint2*>(&g_X8[e8]) = outv;
    }
}

// ---------------- kernel 2: int8 GEMM, 2 CTAs/SM, magic-bias promotion ----------------
__global__ void __launch_bounds__(256, 2)
gemm_kernel(const float* __restrict__ ws,         // weight_scale [O][32]
            const float* __restrict__ act_scale,  // [2048]
            const float* __restrict__ bias,       // [4096]
            float* __restrict__ out) {            // [M][O]
    extern __shared__ char smem[];
    const uint32_t sbase = smem_u32(smem);
    float* sscale = reinterpret_cast<float*>(smem + SCALE_OFF);

    const int tid  = threadIdx.x;
    const int lane = tid & 31;
    const int wid  = tid >> 5;
    const int wm   = wid & 3;       // 4 warps along M (32 rows each)
    const int wn   = wid >> 2;      // 2 warps along N (32 cols each)
    const int n0   = blockIdx.x * BN;
    const int m0   = blockIdx.y * BM;

    // ---- preload per-column group scales: sscale[g*PITCH + nl] = ws[(n0+nl)*32+g]
#pragma unroll
    for (int i = tid; i < BN * 32; i += 256) {
        int nl = i >> 5, g = i & 31;
        sscale[g * SCALE_PITCH + nl] = __ldg(&ws[(size_t)(n0 + nl) * 32 + g]);
    }

    // ---- per-thread ldmatrix address precompute
    const int mi = lane >> 3;          // matrix index 0..3
    const int rr = lane & 7;
    const int c0 = mi >> 1;            // k-half chunk offset
    const int roff = (mi & 1) * 8;
    int rowA[2], rowB[2];
#pragma unroll
    for (int mb = 0; mb < 2; mb++) rowA[mb] = wm * 32 + mb * 16 + roff + rr;
#pragma unroll
    for (int nb = 0; nb < 2; nb++) rowB[nb] = wn * 32 + nb * 16 + roff + rr;

    // ---- accumulators (int accum seeded with magic bias)
    int   ai[2][4][4];
    float af[2][4][4];
#pragma unroll
    for (int mb = 0; mb < 2; mb++)
#pragma unroll
        for (int bb = 0; bb < 4; bb++)
#pragma unroll
            for (int r = 0; r < 4; r++) { ai[mb][bb][r] = MAGIC_I; af[mb][bb][r] = 0.f; }

    // ---- stage loader (cp.async, XOR-swizzled 16B chunks)
    auto load_stage = [&](int ks, int slot) {
        const uint32_t sA = sbase + slot * STAGE_BYTES;
        const uint32_t sB = sA + A_STG;
        const int8_t* gA = g_X8 + (size_t)m0 * I_DIM + ks * BK;
        const int8_t* gB = g_W8 + (size_t)n0 * I_DIM + ks * BK;
#pragma unroll
        for (int i = 0; i < 4; i++) {         // A: 128 rows x 8 chunks = 1024
            int idx = tid + i * 256;
            int row = idx >> 3, ch = idx & 7;
            uint32_t sw = (uint32_t)(row * 128 + ((ch ^ (row & 7)) << 4));
            CP_ASYNC16(sA + sw, gA + (size_t)row * I_DIM + ch * 16);
        }
#pragma unroll
        for (int i = 0; i < 2; i++) {         // B: 64 rows x 8 chunks = 512
            int idx = tid + i * 256;
            int row = idx >> 3, ch = idx & 7;
            uint32_t sw = (uint32_t)(row * 128 + ((ch ^ (row & 7)) << 4));
            CP_ASYNC16(sB + sw, gB + (size_t)row * I_DIM + ch * 16);
        }
    };

    // ---- prologue: fill 3 of 4 stages
    for (int s = 0; s < STAGES - 1; s++) { load_stage(s, s); CP_COMMIT(); }

    const int q2 = (lane & 3) * 2;

    for (int ks = 0; ks < NKS; ks++) {
        CP_WAIT2();
        __syncthreads();
        const int pre = ks + STAGES - 1;
        if (pre < NKS) load_stage(pre, pre & (STAGES - 1));
        CP_COMMIT();

        const uint32_t sA = sbase + (ks & (STAGES - 1)) * STAGE_BYTES;
        const uint32_t sB = sA + A_STG;

#pragma unroll
        for (int kk = 0; kk < 4; kk++) {
            uint32_t a[2][4], br[2][4];
#pragma unroll
            for (int mb = 0; mb < 2; mb++) {
                int row = rowA[mb];
                uint32_t ad = sA + row * 128 + (((((uint32_t)kk << 1) | c0) ^ (row & 7)) << 4);
                LDSM_X4(a[mb][0], a[mb][1], a[mb][2], a[mb][3], ad);
            }
#pragma unroll
            for (int nb = 0; nb < 2; nb++) {
                int row = rowB[nb];
                uint32_t bd = sB + row * 128 + (((((uint32_t)kk << 1) | c0) ^ (row & 7)) << 4);
                LDSM_X4(br[nb][0], br[nb][1], br[nb][2], br[nb][3], bd);
            }
#pragma unroll
            for (int mb = 0; mb < 2; mb++) {
#pragma unroll
                for (int bb = 0; bb < 4; bb++) {
                    const int nb = bb >> 1, e = bb & 1;
                    MMA_S8(ai[mb][bb], a[mb], br[nb][e], br[nb][2 + e]);
                }
            }
        }

        // ---- promote this group's sums into float accumulators (exact, no I2F)
#pragma unroll
        for (int bb = 0; bb < 4; bb++) {
            const int nl = wn * 32 + bb * 8 + q2;
            const float s0 = sscale[ks * SCALE_PITCH + nl];
            const float s1 = sscale[ks * SCALE_PITCH + nl + 1];
#pragma unroll
            for (int mb = 0; mb < 2; mb++) {
                af[mb][bb][0] = __fmaf_rn(s0, __int_as_float(ai[mb][bb][0]) - MAGIC_F, af[mb][bb][0]);
                af[mb][bb][1] = __fmaf_rn(s1, __int_as_float(ai[mb][bb][1]) - MAGIC_F, af[mb][bb][1]);
                af[mb][bb][2] = __fmaf_rn(s0, __int_as_float(ai[mb][bb][2]) - MAGIC_F, af[mb][bb][2]);
                af[mb][bb][3] = __fmaf_rn(s1, __int_as_float(ai[mb][bb][3]) - MAGIC_F, af[mb][bb][3]);
                ai[mb][bb][0] = MAGIC_I; ai[mb][bb][1] = MAGIC_I;
                ai[mb][bb][2] = MAGIC_I; ai[mb][bb][3] = MAGIC_I;
            }
        }
    }

    // ---- epilogue: out = af * act_scale[m] + bias[n]
#pragma unroll
    for (int mb = 0; mb < 2; mb++) {
        const int r0 = m0 + wm * 32 + mb * 16 + (lane >> 2);
        const int r1 = r0 + 8;
        const float sa0 = __ldg(&act_scale[r0 & (S_DIM - 1)]);
        const float sa1 = __ldg(&act_scale[r1 & (S_DIM - 1)]);
#pragma unroll
        for (int bb = 0; bb < 4; bb++) {
            const int n = n0 + wn * 32 + bb * 8 + q2;
            const float2 bv = *reinterpret_cast<const float2*>(bias + n);
            float2 o0, o1;
            o0.x = af[mb][bb][0] * sa0 + bv.x;
            o0.y = af[mb][bb][1] * sa0 + bv.y;
            o1.x = af[mb][bb][2] * sa1 + bv.x;
            o1.y = af[mb][bb][3] * sa1 + bv.y;
            *reinterpret_cast<float2*>(out + (size_t)r0 * O_DIM + n) = o0;
            *reinterpret_cast<float2*>(out + (size_t)r1 * O_DIM + n) = o1;
        }
    }
}

// ---------------- host launcher ----------------
extern "C" void kernel_launch(void* const* d_in, const int* in_sizes, int n_in,
                              void* d_out, int out_size) {
    const float* x    = (const float*)d_in[0];
    const int*   qw   = (const int*)d_in[1];
    const float* as_  = (const float*)d_in[2];
    const float* ws   = (const float*)d_in[3];
    const int*   wz   = (const int*)d_in[4];
    const float* bias = (const float*)d_in[5];
    float* out = (float*)d_out;

    prep_kernel<<<WB + QB, 256>>>(qw, wz, x, as_);

    cudaFuncSetAttribute(gemm_kernel, cudaFuncAttributeMaxDynamicSharedMemorySize,
                         SMEM_TOTAL);
    gemm_kernel<<<dim3(O_DIM / BN, M_TOT / BM), 256, SMEM_TOTAL>>>(ws, as_, bias, out);
}

// round 8
// speedup vs baseline: 1.0426x; 1.0268x over previous
#include <cuda_runtime.h>
#include <cuda_fp16.h>
#include <cstdint>
#include <cstddef>

// ---------------- problem constants ----------------
#define O_DIM 4096
#define I_DIM 4096
#define S_DIM 2048
#define M_TOT 8192            // B*S = 4*2048

// ---------------- GEMM tiling ----------------
#define BM 128
#define BN 64
#define BK 128                // int8 elements per stage = one scale group
#define STAGES 4
#define NKS (I_DIM / BK)      // 32 k-stages
#define A_STG (BM * BK)       // 16384 B
#define B_STG (BN * BK)       // 8192 B
#define STAGE_BYTES (A_STG + B_STG)          // 24576
#define SCALE_OFF (STAGES * STAGE_BYTES)     // 98304
#define SCALE_PITCH 65                       // padded floats per group row (BN=64)
#define SMEM_TOTAL (SCALE_OFF + 32 * SCALE_PITCH * 4)  // 106624  (x2 CTAs fits 228KB/SM)

// magic-bias int->float exact conversion (|P| < 2^22)
#define MAGIC_I 0x4B400000
#define MAGIC_F 12582912.0f

// ---------------- device scratch ----------------
__device__ int8_t g_W8[(size_t)O_DIM * I_DIM];   // w_int - zero, int8 [O][I]
__device__ int8_t g_X8[(size_t)M_TOT * I_DIM];   // quantized activations [M][I]

// ---------------- asm helpers ----------------
__device__ __forceinline__ uint32_t smem_u32(const void* p) {
    uint32_t a;
    asm("{ .reg .u64 t; cvta.to.shared.u64 t, %1; cvt.u32.u64 %0, t; }" : "=r"(a) : "l"(p));
    return a;
}
#define CP_ASYNC16(saddr, gptr) \
    asm volatile("cp.async.cg.shared.global [%0], [%1], 16;" :: "r"(saddr), "l"(gptr) : "memory")
#define CP_COMMIT() asm volatile("cp.async.commit_group;" ::: "memory")
#define CP_WAIT2()  asm volatile("cp.async.wait_group 2;" ::: "memory")

#define LDSM_X4(r0, r1, r2, r3, addr)                                              \
    asm volatile("ldmatrix.sync.aligned.m8n8.x4.shared.b16 {%0,%1,%2,%3}, [%4];"   \
                 : "=r"(r0), "=r"(r1), "=r"(r2), "=r"(r3) : "r"(addr))

#define MMA_S8(c, a, b0_, b1_)                                                     \
    asm volatile("mma.sync.aligned.m16n8k32.row.col.s32.s8.s8.s32 "                \
                 "{%0,%1,%2,%3}, {%4,%5,%6,%7}, {%8,%9}, {%0,%1,%2,%3};"           \
                 : "+r"((c)[0]), "+r"((c)[1]), "+r"((c)[2]), "+r"((c)[3])          \
                 : "r"((a)[0]), "r"((a)[1]), "r"((a)[2]), "r"((a)[3]),             \
                   "r"(b0_), "r"(b1_))

// ---------------- kernel 1: fused prep (wpack + quant) ----------------
#define WB (O_DIM * 2048 / 4 / 256)                    // 8192 blocks: weight pack
#define QB ((int)((size_t)M_TOT * I_DIM / 8 / 256))    // 16384 blocks: activation quant

__global__ void prep_kernel(const int* __restrict__ qw, const int* __restrict__ wz,
                            const float* __restrict__ x, const float* __restrict__ as_) {
    if (blockIdx.x < WB) {
        int t = blockIdx.x * blockDim.x + threadIdx.x;
        int o = t >> 9;
        int j = (t & 511) * 4;              // int32 index within row
        int g = j >> 6;                     // group = (2j)/128
        int z = __ldg(&wz[o * 32 + g]);
        int4 q = *reinterpret_cast<const int4*>(qw + (size_t)o * 2048 + j);
        int qs[4] = {q.x, q.y, q.z, q.w};
        uint32_t lo = 0, hi = 0;
#pragma unroll
        for (int r = 0; r < 2; r++) {
            lo |= (uint32_t)(uint8_t)((qs[r] & 15) - z) << (r * 16);
            lo |= (uint32_t)(uint8_t)(((qs[r] >> 4) & 15) - z) << (r * 16 + 8);
            hi |= (uint32_t)(uint8_t)((qs[r + 2] & 15) - z) << (r * 16);
            hi |= (uint32_t)(uint8_t)(((qs[r + 2] >> 4) & 15) - z) << (r * 16 + 8);
        }
        uint2 outv; outv.x = lo; outv.y = hi;
        *reinterpret_cast<uint2*>(&g_W8[(size_t)o * I_DIM + j * 2]) = outv;
    } else {
        int t = (blockIdx.x - WB) * blockDim.x + threadIdx.x;
        size_t e8 = (size_t)t * 8;
        int m = (int)(e8 >> 12);
        float s = __ldg(&as_[m & (S_DIM - 1)]);
        float4 v0 = *reinterpret_cast<const float4*>(x + e8);
        float4 v1 = *reinterpret_cast<const float4*>(x + e8 + 4);
        float vv[8] = {v0.x, v0.y, v0.z, v0.w, v1.x, v1.y, v1.z, v1.w};
        uint32_t lo = 0, hi = 0;
#pragma unroll
        for (int i = 0; i < 4; i++) {
            int n = (int)rintf(vv[i] / s);
            n = max(-127, min(127, n));
            lo |= ((uint32_t)(uint8_t)(int8_t)n) << (i * 8);
        }
#pragma unroll
        for (int i = 0; i < 4; i++) {
            int n = (int)rintf(vv[4 + i] / s);
            n = max(-127, min(127, n));
            hi |= ((uint32_t)(uint8_t)(int8_t)n) << (i * 8);
        }
        uint2 outv; outv.x = lo; outv.y = hi;
        *reinterpret_cast<uint2*>(&g_X8[e8]) = outv;
    }
}

// ---------------- kernel 2: int8 GEMM, software-pipelined warp body ----------------
__global__ void __launch_bounds__(256, 2)
gemm_kernel(const float* __restrict__ ws,         // weight_scale [O][32]
            const float* __restrict__ act_scale,  // [2048]
            const float* __restrict__ bias,       // [4096]
            float* __restrict__ out) {            // [M][O]
    extern __shared__ char smem[];
    const uint32_t sbase = smem_u32(smem);
    float* sscale = reinterpret_cast<float*>(smem + SCALE_OFF);

    const int tid  = threadIdx.x;
    const int lane = tid & 31;
    const int wid  = tid >> 5;
    const int wm   = wid & 3;       // 4 warps along M (32 rows each)
    const int wn   = wid >> 2;      // 2 warps along N (32 cols each)
    const int n0   = blockIdx.x * BN;
    const int m0   = blockIdx.y * BM;

    // ---- preload per-column group scales
#pragma unroll
    for (int i = tid; i < BN * 32; i += 256) {
        int nl = i >> 5, g = i & 31;
        sscale[g * SCALE_PITCH + nl] = __ldg(&ws[(size_t)(n0 + nl) * 32 + g]);
    }

    // ---- per-thread ldmatrix address precompute
    const int mi = lane >> 3;          // matrix index 0..3
    const int rr = lane & 7;
    const int c0 = mi >> 1;            // k-half chunk offset
    const int roff = (mi & 1) * 8;
    int rowA[2], rowB[2];
#pragma unroll
    for (int mb = 0; mb < 2; mb++) rowA[mb] = wm * 32 + mb * 16 + roff + rr;
#pragma unroll
    for (int nb = 0; nb < 2; nb++) rowB[nb] = wn * 32 + nb * 16 + roff + rr;

    // ---- accumulators (int accum seeded with magic bias) + double-buffered frags
    int      ai[2][4][4];
    float    af[2][4][4];
    uint32_t aF[2][2][4];   // [buf][mb][reg]
    uint32_t bF[2][2][4];   // [buf][nb][reg]
#pragma unroll
    for (int mb = 0; mb < 2; mb++)
#pragma unroll
        for (int bb = 0; bb < 4; bb++)
#pragma unroll
            for (int r = 0; r < 4; r++) { ai[mb][bb][r] = MAGIC_I; af[mb][bb][r] = 0.f; }

    // ---- stage loader (cp.async, XOR-swizzled 16B chunks)
    auto load_stage = [&](int ks, int slot) {
        const uint32_t sA = sbase + slot * STAGE_BYTES;
        const uint32_t sB = sA + A_STG;
        const int8_t* gA = g_X8 + (size_t)m0 * I_DIM + ks * BK;
        const int8_t* gB = g_W8 + (size_t)n0 * I_DIM + ks * BK;
#pragma unroll
        for (int i = 0; i < 4; i++) {         // A: 128 rows x 8 chunks
            int idx = tid + i * 256;
            int row = idx >> 3, ch = idx & 7;
            uint32_t sw = (uint32_t)(row * 128 + ((ch ^ (row & 7)) << 4));
            CP_ASYNC16(sA + sw, gA + (size_t)row * I_DIM + ch * 16);
        }
#pragma unroll
        for (int i = 0; i < 2; i++) {         // B: 64 rows x 8 chunks
            int idx = tid + i * 256;
            int row = idx >> 3, ch = idx & 7;
            uint32_t sw = (uint32_t)(row * 128 + ((ch ^ (row & 7)) << 4));
            CP_ASYNC16(sB + sw, gB + (size_t)row * I_DIM + ch * 16);
        }
    };

    // fragment loader for one kk chunk into buffer buf
    auto ldsm_kk = [&](uint32_t sA, uint32_t sB, int kk, int buf) {
#pragma unroll
        for (int mb = 0; mb < 2; mb++) {
            int row = rowA[mb];
            uint32_t ad = sA + row * 128 + (((((uint32_t)kk << 1) | c0) ^ (row & 7)) << 4);
            LDSM_X4(aF[buf][mb][0], aF[buf][mb][1], aF[buf][mb][2], aF[buf][mb][3], ad);
        }
#pragma unroll
        for (int nb = 0; nb < 2; nb++) {
            int row = rowB[nb];
            uint32_t bd = sB + row * 128 + (((((uint32_t)kk << 1) | c0) ^ (row & 7)) << 4);
            LDSM_X4(bF[buf][nb][0], bF[buf][nb][1], bF[buf][nb][2], bF[buf][nb][3], bd);
        }
    };

    const int q2 = (lane & 3) * 2;

    // promote group `g` int sums into float accumulators, reset ai (exact, no I2F)
    auto promote = [&](int g) {
#pragma unroll
        for (int bb = 0; bb < 4; bb++) {
            const int nl = wn * 32 + bb * 8 + q2;
            const float s0 = sscale[g * SCALE_PITCH + nl];
            const float s1 = sscale[g * SCALE_PITCH + nl + 1];
#pragma unroll
            for (int mb = 0; mb < 2; mb++) {
                af[mb][bb][0] = __fmaf_rn(s0, __int_as_float(ai[mb][bb][0]) - MAGIC_F, af[mb][bb][0]);
                af[mb][bb][1] = __fmaf_rn(s1, __int_as_float(ai[mb][bb][1]) - MAGIC_F, af[mb][bb][1]);
                af[mb][bb][2] = __fmaf_rn(s0, __int_as_float(ai[mb][bb][2]) - MAGIC_F, af[mb][bb][2]);
                af[mb][bb][3] = __fmaf_rn(s1, __int_as_float(ai[mb][bb][3]) - MAGIC_F, af[mb][bb][3]);
                ai[mb][bb][0] = MAGIC_I; ai[mb][bb][1] = MAGIC_I;
                ai[mb][bb][2] = MAGIC_I; ai[mb][bb][3] = MAGIC_I;
            }
        }
    };

    // ---- prologue: fill 3 of 4 stages
    for (int s = 0; s < STAGES - 1; s++) { load_stage(s, s); CP_COMMIT(); }

    for (int ks = 0; ks < NKS; ks++) {
        CP_WAIT2();
        __syncthreads();
        const int pre = ks + STAGES - 1;
        if (pre < NKS) load_stage(pre, pre & (STAGES - 1));
        CP_COMMIT();

        const uint32_t sA = sbase + (ks & (STAGES - 1)) * STAGE_BYTES;
        const uint32_t sB = sA + A_STG;

        // first fragment load of this stage in flight...
        ldsm_kk(sA, sB, 0, 0);
        // ...while we promote the previous stage's group (fills the LDSM latency window)
        if (ks > 0) promote(ks - 1);

#pragma unroll
        for (int kk = 0; kk < 4; kk++) {
            if (kk < 3) ldsm_kk(sA, sB, kk + 1, (kk + 1) & 1);   // prefetch next chunk
            const int buf = kk & 1;
#pragma unroll
            for (int mb = 0; mb < 2; mb++) {
#pragma unroll
                for (int bb = 0; bb < 4; bb++) {
                    const int nb = bb >> 1, e = bb & 1;
                    MMA_S8(ai[mb][bb], aF[buf][mb], bF[buf][nb][e], bF[buf][nb][2 + e]);
                }
            }
        }
    }
    promote(NKS - 1);

    // ---- epilogue: out = af * act_scale[m] + bias[n]
#pragma unroll
    for (int mb = 0; mb < 2; mb++) {
        const int r0 = m0 + wm * 32 + mb * 16 + (lane >> 2);
        const int r1 = r0 + 8;
        const float sa0 = __ldg(&act_scale[r0 & (S_DIM - 1)]);
        const float sa1 = __ldg(&act_scale[r1 & (S_DIM - 1)]);
#pragma unroll
        for (int bb = 0; bb < 4; bb++) {
            const int n = n0 + wn * 32 + bb * 8 + q2;
            const float2 bv = *reinterpret_cast<const float2*>(bias + n);
            float2 o0, o1;
            o0.x = af[mb][bb][0] * sa0 + bv.x;
            o0.y = af[mb][bb][1] * sa0 + bv.y;
            o1.x = af[mb][bb][2] * sa1 + bv.x;
            o1.y = af[mb][bb][3] * sa1 + bv.y;
            *reinterpret_cast<float2*>(out + (size_t)r0 * O_DIM + n) = o0;
            *reinterpret_cast<float2*>(out + (size_t)r1 * O_DIM + n) = o1;
        }
    }
}

// ---------------- host launcher ----------------
extern "C" void kernel_launch(void* const* d_in, const int* in_sizes, int n_in,
                              void* d_out, int out_size) {
    const float* x    = (const float*)d_in[0];
    const int*   qw   = (const int*)d_in[1];
    const float* as_  = (const float*)d_in[2];
    const float* ws   = (const float*)d_in[3];
    const int*   wz   = (const int*)d_in[4];
    const float* bias = (const float*)d_in[5];
    float* out = (float*)d_out;

    prep_kernel<<<WB + QB, 256>>>(qw, wz, x, as_);

    cudaFuncSetAttribute(gemm_kernel, cudaFuncAttributeMaxDynamicSharedMemorySize,
                         SMEM_TOTAL);
    gemm_kernel<<<dim3(O_DIM / BN, M_TOT / BM), 256, SMEM_TOTAL>>>(ws, as_, bias, out);
}

// round 9
// speedup vs baseline: 1.0834x; 1.0391x over previous
#include <cuda_runtime.h>
#include <cuda_fp16.h>
#include <cstdint>
#include <cstddef>

// ---------------- problem constants ----------------
#define O_DIM 4096
#define I_DIM 4096
#define S_DIM 2048
#define M_TOT 8192            // B*S = 4*2048

// ---------------- GEMM tiling ----------------
#define BM 128
#define BN 64
#define BK 128                // int8 elements per stage = one scale group
#define STAGES 4
#define NKS (I_DIM / BK)      // 32 k-stages
#define A_STG (BM * BK)       // 16384 B
#define B_STG (BN * BK)       // 8192 B
#define STAGE_BYTES (A_STG + B_STG)          // 24576
#define SCALE_OFF (STAGES * STAGE_BYTES)     // 98304
#define SCALE_PITCH 65                       // padded floats per group row (BN=64)
#define SMEM_TOTAL (SCALE_OFF + 32 * SCALE_PITCH * 4)  // 106624  (x2 CTAs fits 228KB/SM)

// magic-bias int->float exact conversion (|P| < 2^22)
#define MAGIC_I 0x4B400000
#define MAGIC_F 12582912.0f

// ---------------- device scratch ----------------
__device__ int8_t g_W8[(size_t)O_DIM * I_DIM];   // w_int - zero, int8 [O][I]
__device__ int8_t g_X8[(size_t)M_TOT * I_DIM];   // quantized activations [M][I]

// ---------------- asm helpers ----------------
__device__ __forceinline__ uint32_t smem_u32(const void* p) {
    uint32_t a;
    asm("{ .reg .u64 t; cvta.to.shared.u64 t, %1; cvt.u32.u64 %0, t; }" : "=r"(a) : "l"(p));
    return a;
}
#define CP_ASYNC16(saddr, gptr) \
    asm volatile("cp.async.cg.shared.global [%0], [%1], 16;" :: "r"(saddr), "l"(gptr) : "memory")
#define CP_COMMIT() asm volatile("cp.async.commit_group;" ::: "memory")
#define CP_WAIT2()  asm volatile("cp.async.wait_group 2;" ::: "memory")

#define LDSM_X4(r0, r1, r2, r3, addr)                                              \
    asm volatile("ldmatrix.sync.aligned.m8n8.x4.shared.b16 {%0,%1,%2,%3}, [%4];"   \
                 : "=r"(r0), "=r"(r1), "=r"(r2), "=r"(r3) : "r"(addr))

// accumulate form: C==D
#define MMA_S8(c, a, b0_, b1_)                                                     \
    asm volatile("mma.sync.aligned.m16n8k32.row.col.s32.s8.s8.s32 "                \
                 "{%0,%1,%2,%3}, {%4,%5,%6,%7}, {%8,%9}, {%0,%1,%2,%3};"           \
                 : "+r"((c)[0]), "+r"((c)[1]), "+r"((c)[2]), "+r"((c)[3])          \
                 : "r"((a)[0]), "r"((a)[1]), "r"((a)[2]), "r"((a)[3]),             \
                   "r"(b0_), "r"(b1_))

// init form: D = A*B + {mc,mc,mc,mc}  (replaces per-group accumulator resets)
#define MMA_S8_INIT(c, a, b0_, b1_, mc)                                            \
    asm volatile("mma.sync.aligned.m16n8k32.row.col.s32.s8.s8.s32 "                \
                 "{%0,%1,%2,%3}, {%4,%5,%6,%7}, {%8,%9}, {%10,%10,%10,%10};"       \
                 : "=r"((c)[0]), "=r"((c)[1]), "=r"((c)[2]), "=r"((c)[3])          \
                 : "r"((a)[0]), "r"((a)[1]), "r"((a)[2]), "r"((a)[3]),             \
                   "r"(b0_), "r"(b1_), "r"(mc))

// ---------------- kernel 1: fused prep (wpack + quant) ----------------
#define WB (O_DIM * 2048 / 4 / 256)                    // 8192 blocks: weight pack
#define QB ((int)((size_t)M_TOT * I_DIM / 8 / 256))    // 16384 blocks: activation quant

__global__ void prep_kernel(const int* __restrict__ qw, const int* __restrict__ wz,
                            const float* __restrict__ x, const float* __restrict__ as_) {
    if (blockIdx.x < WB) {
        int t = blockIdx.x * blockDim.x + threadIdx.x;
        int o = t >> 9;
        int j = (t & 511) * 4;              // int32 index within row
        int g = j >> 6;                     // group = (2j)/128
        int z = __ldg(&wz[o * 32 + g]);
        int4 q = *reinterpret_cast<const int4*>(qw + (size_t)o * 2048 + j);
        int qs[4] = {q.x, q.y, q.z, q.w};
        uint32_t lo = 0, hi = 0;
#pragma unroll
        for (int r = 0; r < 2; r++) {
            lo |= (uint32_t)(uint8_t)((qs[r] & 15) - z) << (r * 16);
            lo |= (uint32_t)(uint8_t)(((qs[r] >> 4) & 15) - z) << (r * 16 + 8);
            hi |= (uint32_t)(uint8_t)((qs[r + 2] & 15) - z) << (r * 16);
            hi |= (uint32_t)(uint8_t)(((qs[r + 2] >> 4) & 15) - z) << (r * 16 + 8);
        }
        uint2 outv; outv.x = lo; outv.y = hi;
        *reinterpret_cast<uint2*>(&g_W8[(size_t)o * I_DIM + j * 2]) = outv;
    } else {
        int t = (blockIdx.x - WB) * blockDim.x + threadIdx.x;
        size_t e8 = (size_t)t * 8;
        int m = (int)(e8 >> 12);
        float s = __ldg(&as_[m & (S_DIM - 1)]);
        float4 v0 = *reinterpret_cast<const float4*>(x + e8);
        float4 v1 = *reinterpret_cast<const float4*>(x + e8 + 4);
        float vv[8] = {v0.x, v0.y, v0.z, v0.w, v1.x, v1.y, v1.z, v1.w};
        uint32_t lo = 0, hi = 0;
#pragma unroll
        for (int i = 0; i < 4; i++) {
            int n = (int)rintf(vv[i] / s);
            n = max(-127, min(127, n));
            lo |= ((uint32_t)(uint8_t)(int8_t)n) << (i * 8);
        }
#pragma unroll
        for (int i = 0; i < 4; i++) {
            int n = (int)rintf(vv[4 + i] / s);
            n = max(-127, min(127, n));
            hi |= ((uint32_t)(uint8_t)(int8_t)n) << (i * 8);
        }
        uint2 outv; outv.x = lo; outv.y = hi;
        *reinterpret_cast<uint2*>(&g_X8[e8]) = outv;
    }
}

// ---------------- kernel 2: int8 GEMM, instruction-diet body ----------------
__global__ void __launch_bounds__(256, 2)
gemm_kernel(const float* __restrict__ ws,         // weight_scale [O][32]
            const float* __restrict__ act_scale,  // [2048]
            const float* __restrict__ bias,       // [4096]
            float* __restrict__ out) {            // [M][O]
    extern __shared__ char smem[];
    const uint32_t sbase = smem_u32(smem);
    float* sscale = reinterpret_cast<float*>(smem + SCALE_OFF);

    const int tid  = threadIdx.x;
    const int lane = tid & 31;
    const int wid  = tid >> 5;
    const int wm   = wid & 3;       // 4 warps along M (32 rows each)
    const int wn   = wid >> 2;      // 2 warps along N (32 cols each)
    const int n0   = blockIdx.x * BN;
    const int m0   = blockIdx.y * BM;

    // ---- preload per-column group scales
#pragma unroll
    for (int i = tid; i < BN * 32; i += 256) {
        int nl = i >> 5, g = i & 31;
        sscale[g * SCALE_PITCH + nl] = __ldg(&ws[(size_t)(n0 + nl) * 32 + g]);
    }

    // ---- per-thread ldmatrix address precompute
    const int mi = lane >> 3;          // matrix index 0..3
    const int rr = lane & 7;
    const int c0 = mi >> 1;            // k-half chunk offset
    const int roff = (mi & 1) * 8;
    // all fragment rows are (multiple of 8) + rr  =>  row & 7 == rr for every frag;
    // the per-kk swizzle offset is shared by all 6 LDSMs of a chunk:
    uint32_t swoff[4];
#pragma unroll
    for (int kk = 0; kk < 4; kk++)
        swoff[kk] = (uint32_t)(((((kk << 1) | c0)) ^ rr) << 4);
    uint32_t rowA128[2], rowB128[2];
#pragma unroll
    for (int mb = 0; mb < 2; mb++) rowA128[mb] = (uint32_t)((wm * 32 + mb * 16 + roff + rr) * 128);
#pragma unroll
    for (int nb = 0; nb < 2; nb++) rowB128[nb] = (uint32_t)((wn * 32 + nb * 16 + roff + rr) * 128);

    // ---- accumulators + double-buffered frags
    int      ai[2][4][4];        // written fresh each stage by MMA_S8_INIT (no resets)
    float    af[2][4][4];
    uint32_t aF[2][2][4];        // [buf][mb][reg]
    uint32_t bF[2][2][4];        // [buf][nb][reg]
    const int magic_c = MAGIC_I;
#pragma unroll
    for (int mb = 0; mb < 2; mb++)
#pragma unroll
        for (int bb = 0; bb < 4; bb++)
#pragma unroll
            for (int r = 0; r < 4; r++) af[mb][bb][r] = 0.f;

    // ---- stage loader (cp.async, XOR-swizzled 16B chunks)
    auto load_stage = [&](int ks, int slot) {
        const uint32_t sA = sbase + slot * STAGE_BYTES;
        const uint32_t sB = sA + A_STG;
        const int8_t* gA = g_X8 + (size_t)m0 * I_DIM + ks * BK;
        const int8_t* gB = g_W8 + (size_t)n0 * I_DIM + ks * BK;
#pragma unroll
        for (int i = 0; i < 4; i++) {         // A: 128 rows x 8 chunks
            int idx = tid + i * 256;
            int row = idx >> 3, ch = idx & 7;
            uint32_t sw = (uint32_t)(row * 128 + ((ch ^ (row & 7)) << 4));
            CP_ASYNC16(sA + sw, gA + (size_t)row * I_DIM + ch * 16);
        }
#pragma unroll
        for (int i = 0; i < 2; i++) {         // B: 64 rows x 8 chunks
            int idx = tid + i * 256;
            int row = idx >> 3, ch = idx & 7;
            uint32_t sw = (uint32_t)(row * 128 + ((ch ^ (row & 7)) << 4));
            CP_ASYNC16(sB + sw, gB + (size_t)row * I_DIM + ch * 16);
        }
    };

    // fragment loader for one kk chunk into buffer buf
    auto ldsm_kk = [&](uint32_t sA, uint32_t sB, int kk, int buf) {
        const uint32_t so = swoff[kk];
#pragma unroll
        for (int mb = 0; mb < 2; mb++) {
            uint32_t ad = sA + rowA128[mb] + so;
            LDSM_X4(aF[buf][mb][0], aF[buf][mb][1], aF[buf][mb][2], aF[buf][mb][3], ad);
        }
#pragma unroll
        for (int nb = 0; nb < 2; nb++) {
            uint32_t bd = sB + rowB128[nb] + so;
            LDSM_X4(bF[buf][nb][0], bF[buf][nb][1], bF[buf][nb][2], bF[buf][nb][3], bd);
        }
    };

    const int q2 = (lane & 3) * 2;

    // promote group `g` int sums into float accumulators (read-only on ai now)
    auto promote = [&](int g) {
#pragma unroll
        for (int bb = 0; bb < 4; bb++) {
            const int nl = wn * 32 + bb * 8 + q2;
            const float s0 = sscale[g * SCALE_PITCH + nl];
            const float s1 = sscale[g * SCALE_PITCH + nl + 1];
#pragma unroll
            for (int mb = 0; mb < 2; mb++) {
                af[mb][bb][0] = __fmaf_rn(s0, __int_as_float(ai[mb][bb][0]) - MAGIC_F, af[mb][bb][0]);
                af[mb][bb][1] = __fmaf_rn(s1, __int_as_float(ai[mb][bb][1]) - MAGIC_F, af[mb][bb][1]);
                af[mb][bb][2] = __fmaf_rn(s0, __int_as_float(ai[mb][bb][2]) - MAGIC_F, af[mb][bb][2]);
                af[mb][bb][3] = __fmaf_rn(s1, __int_as_float(ai[mb][bb][3]) - MAGIC_F, af[mb][bb][3]);
            }
        }
    };

    // ---- prologue: fill 3 of 4 stages
    for (int s = 0; s < STAGES - 1; s++) { load_stage(s, s); CP_COMMIT(); }

    for (int ks = 0; ks < NKS; ks++) {
        CP_WAIT2();
        __syncthreads();
        const int pre = ks + STAGES - 1;
        if (pre < NKS) load_stage(pre, pre & (STAGES - 1));
        CP_COMMIT();

        const uint32_t sA = sbase + (ks & (STAGES - 1)) * STAGE_BYTES;
        const uint32_t sB = sA + A_STG;

        // first fragment load of this stage in flight...
        ldsm_kk(sA, sB, 0, 0);
        // ...promote previous group while LDSM latency drains (reads ai, then kk0 INIT rewrites it)
        if (ks > 0) promote(ks - 1);

#pragma unroll
        for (int kk = 0; kk < 4; kk++) {
            if (kk < 3) ldsm_kk(sA, sB, kk + 1, (kk + 1) & 1);   // prefetch next chunk
            const int buf = kk & 1;
            if (kk == 0) {
#pragma unroll
                for (int mb = 0; mb < 2; mb++)
#pragma unroll
                    for (int bb = 0; bb < 4; bb++) {
                        const int nb = bb >> 1, e = bb & 1;
                        MMA_S8_INIT(ai[mb][bb], aF[buf][mb], bF[buf][nb][e], bF[buf][nb][2 + e], magic_c);
                    }
            } else {
#pragma unroll
                for (int mb = 0; mb < 2; mb++)
#pragma unroll
                    for (int bb = 0; bb < 4; bb++) {
                        const int nb = bb >> 1, e = bb & 1;
                        MMA_S8(ai[mb][bb], aF[buf][mb], bF[buf][nb][e], bF[buf][nb][2 + e]);
                    }
            }
        }
    }
    promote(NKS - 1);

    // ---- epilogue: out = af * act_scale[m] + bias[n]
#pragma unroll
    for (int mb = 0; mb < 2; mb++) {
        const int r0 = m0 + wm * 32 + mb * 16 + (lane >> 2);
        const int r1 = r0 + 8;
        const float sa0 = __ldg(&act_scale[r0 & (S_DIM - 1)]);
        const float sa1 = __ldg(&act_scale[r1 & (S_DIM - 1)]);
#pragma unroll
        for (int bb = 0; bb < 4; bb++) {
            const int n = n0 + wn * 32 + bb * 8 + q2;
            const float2 bv = *reinterpret_cast<const float2*>(bias + n);
            float2 o0, o1;
            o0.x = af[mb][bb][0] * sa0 + bv.x;
            o0.y = af[mb][bb][1] * sa0 + bv.y;
            o1.x = af[mb][bb][2] * sa1 + bv.x;
            o1.y = af[mb][bb][3] * sa1 + bv.y;
            *reinterpret_cast<float2*>(out + (size_t)r0 * O_DIM + n) = o0;
            *reinterpret_cast<float2*>(out + (size_t)r1 * O_DIM + n) = o1;
        }
    }
}

// ---------------- host launcher ----------------
extern "C" void kernel_launch(void* const* d_in, const int* in_sizes, int n_in,
                              void* d_out, int out_size) {
    const float* x    = (const float*)d_in[0];
    const int*   qw   = (const int*)d_in[1];
    const float* as_  = (const float*)d_in[2];
    const float* ws   = (const float*)d_in[3];
    const int*   wz   = (const int*)d_in[4];
    const float* bias = (const float*)d_in[5];
    float* out = (float*)d_out;

    prep_kernel<<<WB + QB, 256>>>(qw, wz, x, as_);

    cudaFuncSetAttribute(gemm_kernel, cudaFuncAttributeMaxDynamicSharedMemorySize,
                         SMEM_TOTAL);
    gemm_kernel<<<dim3(O_DIM / BN, M_TOT / BM), 256, SMEM_TOTAL>>>(ws, as_, bias, out);
}

// round 10
// speedup vs baseline: 1.0879x; 1.0041x over previous
#include <cuda_runtime.h>
#include <cuda_fp16.h>
#include <cstdint>
#include <cstddef>

// ---------------- problem constants ----------------
#define O_DIM 4096
#define I_DIM 4096
#define S_DIM 2048
#define M_TOT 8192            // B*S = 4*2048

// ---------------- GEMM tiling ----------------
#define BM 128
#define BN 64
#define BK 128                // int8 elements per stage = one scale group
#define STAGES 4
#define NKS (I_DIM / BK)      // 32 k-stages
#define A_STG (BM * BK)       // 16384 B
#define B_STG (BN * BK)       // 8192 B
#define STAGE_BYTES (A_STG + B_STG)          // 24576
#define SCALE_OFF (STAGES * STAGE_BYTES)     // 98304
#define SCALE_PITCH 65                       // padded floats per group row (BN=64)
#define SMEM_TOTAL (SCALE_OFF + 32 * SCALE_PITCH * 4)  // 106624  (x2 CTAs fits 228KB/SM)

// magic-bias int->float exact conversion (|P| < 2^22)
#define MAGIC_I 0x4B400000
#define MAGIC_F 12582912.0f

// ---------------- device scratch ----------------
__device__ int8_t g_W8[(size_t)O_DIM * I_DIM];   // w_int - zero, int8 [O][I]
__device__ int8_t g_X8[(size_t)M_TOT * I_DIM];   // quantized activations [M][I]

// ---------------- asm helpers ----------------
__device__ __forceinline__ uint32_t smem_u32(const void* p) {
    uint32_t a;
    asm("{ .reg .u64 t; cvta.to.shared.u64 t, %1; cvt.u32.u64 %0, t; }" : "=r"(a) : "l"(p));
    return a;
}
#define CP_ASYNC16(saddr, gptr) \
    asm volatile("cp.async.cg.shared.global [%0], [%1], 16;" :: "r"(saddr), "l"(gptr) : "memory")
#define CP_COMMIT() asm volatile("cp.async.commit_group;" ::: "memory")
#define CP_WAIT2()  asm volatile("cp.async.wait_group 2;" ::: "memory")

#define LDSM_X4(r0, r1, r2, r3, addr)                                              \
    asm volatile("ldmatrix.sync.aligned.m8n8.x4.shared.b16 {%0,%1,%2,%3}, [%4];"   \
                 : "=r"(r0), "=r"(r1), "=r"(r2), "=r"(r3) : "r"(addr))

// accumulate form: C==D
#define MMA_S8(c, a, b0_, b1_)                                                     \
    asm volatile("mma.sync.aligned.m16n8k32.row.col.s32.s8.s8.s32 "                \
                 "{%0,%1,%2,%3}, {%4,%5,%6,%7}, {%8,%9}, {%0,%1,%2,%3};"           \
                 : "+r"((c)[0]), "+r"((c)[1]), "+r"((c)[2]), "+r"((c)[3])          \
                 : "r"((a)[0]), "r"((a)[1]), "r"((a)[2]), "r"((a)[3]),             \
                   "r"(b0_), "r"(b1_))

// init form: D = A*B + {mc,mc,mc,mc}  (replaces per-group accumulator resets)
#define MMA_S8_INIT(c, a, b0_, b1_, mc)                                            \
    asm volatile("mma.sync.aligned.m16n8k32.row.col.s32.s8.s8.s32 "                \
                 "{%0,%1,%2,%3}, {%4,%5,%6,%7}, {%8,%9}, {%10,%10,%10,%10};"       \
                 : "=r"((c)[0]), "=r"((c)[1]), "=r"((c)[2]), "=r"((c)[3])          \
                 : "r"((a)[0]), "r"((a)[1]), "r"((a)[2]), "r"((a)[3]),             \
                   "r"(b0_), "r"(b1_), "r"(mc))

// ---------------- kernel 1: fused prep (wpack + quant) ----------------
#define WB (O_DIM * 2048 / 4 / 256)                    // 8192 blocks: weight pack
#define QB ((int)((size_t)M_TOT * I_DIM / 8 / 256))    // 16384 blocks: activation quant

__global__ void prep_kernel(const int* __restrict__ qw, const int* __restrict__ wz,
                            const float* __restrict__ x, const float* __restrict__ as_) {
    if (blockIdx.x < WB) {
        int t = blockIdx.x * blockDim.x + threadIdx.x;
        int o = t >> 9;
        int j = (t & 511) * 4;              // int32 index within row
        int g = j >> 6;                     // group = (2j)/128
        int z = __ldg(&wz[o * 32 + g]);
        int4 q = *reinterpret_cast<const int4*>(qw + (size_t)o * 2048 + j);
        int qs[4] = {q.x, q.y, q.z, q.w};
        uint32_t lo = 0, hi = 0;
#pragma unroll
        for (int r = 0; r < 2; r++) {
            lo |= (uint32_t)(uint8_t)((qs[r] & 15) - z) << (r * 16);
            lo |= (uint32_t)(uint8_t)(((qs[r] >> 4) & 15) - z) << (r * 16 + 8);
            hi |= (uint32_t)(uint8_t)((qs[r + 2] & 15) - z) << (r * 16);
            hi |= (uint32_t)(uint8_t)(((qs[r + 2] >> 4) & 15) - z) << (r * 16 + 8);
        }
        uint2 outv; outv.x = lo; outv.y = hi;
        *reinterpret_cast<uint2*>(&g_W8[(size_t)o * I_DIM + j * 2]) = outv;
    } else {
        int t = (blockIdx.x - WB) * blockDim.x + threadIdx.x;
        size_t e8 = (size_t)t * 8;
        int m = (int)(e8 >> 12);
        float s = __ldg(&as_[m & (S_DIM - 1)]);
        float4 v0 = *reinterpret_cast<const float4*>(x + e8);
        float4 v1 = *reinterpret_cast<const float4*>(x + e8 + 4);
        float vv[8] = {v0.x, v0.y, v0.z, v0.w, v1.x, v1.y, v1.z, v1.w};
        uint32_t lo = 0, hi = 0;
#pragma unroll
        for (int i = 0; i < 4; i++) {
            int n = (int)rintf(vv[i] / s);
            n = max(-127, min(127, n));
            lo |= ((uint32_t)(uint8_t)(int8_t)n) << (i * 8);
        }
#pragma unroll
        for (int i = 0; i < 4; i++) {
            int n = (int)rintf(vv[4 + i] / s);
            n = max(-127, min(127, n));
            hi |= ((uint32_t)(uint8_t)(int8_t)n) << (i * 8);
        }
        uint2 outv; outv.x = lo; outv.y = hi;
        *reinterpret_cast<uint2*>(&g_X8[e8]) = outv;
    }
}

// ---------------- kernel 2: int8 GEMM, instruction-diet body ----------------
__global__ void __launch_bounds__(256, 2)
gemm_kernel(const float* __restrict__ ws,         // weight_scale [O][32]
            const float* __restrict__ act_scale,  // [2048]
            const float* __restrict__ bias,       // [4096]
            float* __restrict__ out) {            // [M][O]
    extern __shared__ char smem[];
    const uint32_t sbase = smem_u32(smem);
    float* sscale = reinterpret_cast<float*>(smem + SCALE_OFF);

    const int tid  = threadIdx.x;
    const int lane = tid & 31;
    const int wid  = tid >> 5;
    const int wm   = wid & 3;       // 4 warps along M (32 rows each)
    const int wn   = wid >> 2;      // 2 warps along N (32 cols each)
    const int n0   = blockIdx.x * BN;
    const int m0   = blockIdx.y * BM;

    // ---- preload per-column group scales
#pragma unroll
    for (int i = tid; i < BN * 32; i += 256) {
        int nl = i >> 5, g = i & 31;
        sscale[g * SCALE_PITCH + nl] = __ldg(&ws[(size_t)(n0 + nl) * 32 + g]);
    }

    // ---- per-thread ldmatrix address precompute
    const int mi = lane >> 3;          // matrix index 0..3
    const int rr = lane & 7;
    const int c0 = mi >> 1;            // k-half chunk offset
    const int roff = (mi & 1) * 8;
    // all fragment rows are (multiple of 8) + rr  =>  row & 7 == rr for every frag;
    // the per-kk swizzle offset is shared by all 6 LDSMs of a chunk:
    uint32_t swoff[4];
#pragma unroll
    for (int kk = 0; kk < 4; kk++)
        swoff[kk] = (uint32_t)(((((kk << 1) | c0)) ^ rr) << 4);
    uint32_t rowA128[2], rowB128[2];
#pragma unroll
    for (int mb = 0; mb < 2; mb++) rowA128[mb] = (uint32_t)((wm * 32 + mb * 16 + roff + rr) * 128);
#pragma unroll
    for (int nb = 0; nb < 2; nb++) rowB128[nb] = (uint32_t)((wn * 32 + nb * 16 + roff + rr) * 128);

    // ---- accumulators + double-buffered frags
    int      ai[2][4][4];        // written fresh each stage by MMA_S8_INIT (no resets)
    float    af[2][4][4];
    uint32_t aF[2][2][4];        // [buf][mb][reg]
    uint32_t bF[2][2][4];        // [buf][nb][reg]
    const int magic_c = MAGIC_I;
#pragma unroll
    for (int mb = 0; mb < 2; mb++)
#pragma unroll
        for (int bb = 0; bb < 4; bb++)
#pragma unroll
            for (int r = 0; r < 4; r++) af[mb][bb][r] = 0.f;

    // ---- stage loader (cp.async, XOR-swizzled 16B chunks)
    auto load_stage = [&](int ks, int slot) {
        const uint32_t sA = sbase + slot * STAGE_BYTES;
        const uint32_t sB = sA + A_STG;
        const int8_t* gA = g_X8 + (size_t)m0 * I_DIM + ks * BK;
        const int8_t* gB = g_W8 + (size_t)n0 * I_DIM + ks * BK;
#pragma unroll
        for (int i = 0; i < 4; i++) {         // A: 128 rows x 8 chunks
            int idx = tid + i * 256;
            int row = idx >> 3, ch = idx & 7;
            uint32_t sw = (uint32_t)(row * 128 + ((ch ^ (row & 7)) << 4));
            CP_ASYNC16(sA + sw, gA + (size_t)row * I_DIM + ch * 16);
        }
#pragma unroll
        for (int i = 0; i < 2; i++) {         // B: 64 rows x 8 chunks
            int idx = tid + i * 256;
            int row = idx >> 3, ch = idx & 7;
            uint32_t sw = (uint32_t)(row * 128 + ((ch ^ (row & 7)) << 4));
            CP_ASYNC16(sB + sw, gB + (size_t)row * I_DIM + ch * 16);
        }
    };

    // fragment loader for one kk chunk into buffer buf
    auto ldsm_kk = [&](uint32_t sA, uint32_t sB, int kk, int buf) {
        const uint32_t so = swoff[kk];
#pragma unroll
        for (int mb = 0; mb < 2; mb++) {
            uint32_t ad = sA + rowA128[mb] + so;
            LDSM_X4(aF[buf][mb][0], aF[buf][mb][1], aF[buf][mb][2], aF[buf][mb][3], ad);
        }
#pragma unroll
        for (int nb = 0; nb < 2; nb++) {
            uint32_t bd = sB + rowB128[nb] + so;
            LDSM_X4(bF[buf][nb][0], bF[buf][nb][1], bF[buf][nb][2], bF[buf][nb][3], bd);
        }
    };

    const int q2 = (lane & 3) * 2;

    // promote group `g` int sums into float accumulators (read-only on ai now)
    auto promote = [&](int g) {
#pragma unroll
        for (int bb = 0; bb < 4; bb++) {
            const int nl = wn * 32 + bb * 8 + q2;
            const float s0 = sscale[g * SCALE_PITCH + nl];
            const float s1 = sscale[g * SCALE_PITCH + nl + 1];
#pragma unroll
            for (int mb = 0; mb < 2; mb++) {
                af[mb][bb][0] = __fmaf_rn(s0, __int_as_float(ai[mb][bb][0]) - MAGIC_F, af[mb][bb][0]);
                af[mb][bb][1] = __fmaf_rn(s1, __int_as_float(ai[mb][bb][1]) - MAGIC_F, af[mb][bb][1]);
                af[mb][bb][2] = __fmaf_rn(s0, __int_as_float(ai[mb][bb][2]) - MAGIC_F, af[mb][bb][2]);
                af[mb][bb][3] = __fmaf_rn(s1, __int_as_float(ai[mb][bb][3]) - MAGIC_F, af[mb][bb][3]);
            }
        }
    };

    // ---- prologue: fill 3 of 4 stages
    for (int s = 0; s < STAGES - 1; s++) { load_stage(s, s); CP_COMMIT(); }

    for (int ks = 0; ks < NKS; ks++) {
        CP_WAIT2();
        __syncthreads();
        const int pre = ks + STAGES - 1;
        if (pre < NKS) load_stage(pre, pre & (STAGES - 1));
        CP_COMMIT();

        const uint32_t sA = sbase + (ks & (STAGES - 1)) * STAGE_BYTES;
        const uint32_t sB = sA + A_STG;

        // first fragment load of this stage in flight...
        ldsm_kk(sA, sB, 0, 0);
        // ...promote previous group while LDSM latency drains (reads ai, then kk0 INIT rewrites it)
        if (ks > 0) promote(ks - 1);

#pragma unroll
        for (int kk = 0; kk < 4; kk++) {
            if (kk < 3) ldsm_kk(sA, sB, kk + 1, (kk + 1) & 1);   // prefetch next chunk
            const int buf = kk & 1;
            if (kk == 0) {
#pragma unroll
                for (int mb = 0; mb < 2; mb++)
#pragma unroll
                    for (int bb = 0; bb < 4; bb++) {
                        const int nb = bb >> 1, e = bb & 1;
                        MMA_S8_INIT(ai[mb][bb], aF[buf][mb], bF[buf][nb][e], bF[buf][nb][2 + e], magic_c);
                    }
            } else {
#pragma unroll
                for (int mb = 0; mb < 2; mb++)
#pragma unroll
                    for (int bb = 0; bb < 4; bb++) {
                        const int nb = bb >> 1, e = bb & 1;
                        MMA_S8(ai[mb][bb], aF[buf][mb], bF[buf][nb][e], bF[buf][nb][2 + e]);
                    }
            }
        }
    }
    promote(NKS - 1);

    // ---- epilogue: out = af * act_scale[m] + bias[n]
#pragma unroll
    for (int mb = 0; mb < 2; mb++) {
        const int r0 = m0 + wm * 32 + mb * 16 + (lane >> 2);
        const int r1 = r0 + 8;
        const float sa0 = __ldg(&act_scale[r0 & (S_DIM - 1)]);
        const float sa1 = __ldg(&act_scale[r1 & (S_DIM - 1)]);
#pragma unroll
        for (int bb = 0; bb < 4; bb++) {
            const int n = n0 + wn * 32 + bb * 8 + q2;
            const float2 bv = *reinterpret_cast<const float2*>(bias + n);
            float2 o0, o1;
            o0.x = af[mb][bb][0] * sa0 + bv.x;
            o0.y = af[mb][bb][1] * sa0 + bv.y;
            o1.x = af[mb][bb][2] * sa1 + bv.x;
            o1.y = af[mb][bb][3] * sa1 + bv.y;
            *reinterpret_cast<float2*>(out + (size_t)r0 * O_DIM + n) = o0;
            *reinterpret_cast<float2*>(out + (size_t)r1 * O_DIM + n) = o1;
        }
    }
}

// ---------------- host launcher ----------------
extern "C" void kernel_launch(void* const* d_in, const int* in_sizes, int n_in,
                              void* d_out, int out_size) {
    const float* x    = (const float*)d_in[0];
    const int*   qw   = (const int*)d_in[1];
    const float* as_  = (const float*)d_in[2];
    const float* ws   = (const float*)d_in[3];
    const int*   wz   = (const int*)d_in[4];
    const float* bias = (const float*)d_in[5];
    float* out = (float*)d_out;

    prep_kernel<<<WB + QB, 256>>>(qw, wz, x, as_);

    cudaFuncSetAttribute(gemm_kernel, cudaFuncAttributeMaxDynamicSharedMemorySize,
                         SMEM_TOTAL);
    gemm_kernel<<<dim3(O_DIM / BN, M_TOT / BM), 256, SMEM_TOTAL>>>(ws, as_, bias, out);
}

// round 11
// speedup vs baseline: 1.0927x; 1.0045x over previous
#include <cuda_runtime.h>
#include <cuda_fp16.h>
#include <cstdint>
#include <cstddef>

// ---------------- problem constants ----------------
#define O_DIM 4096
#define I_DIM 4096
#define S_DIM 2048
#define M_TOT 8192            // B*S = 4*2048

// ---------------- GEMM tiling ----------------
#define BM 128
#define BN 64
#define BK 128                // int8 elements per stage = one scale group
#define STAGES 4
#define NKS (I_DIM / BK)      // 32 k-stages
#define A_STG (BM * BK)       // 16384 B
#define B_STG (BN * BK)       // 8192 B
#define STAGE_BYTES (A_STG + B_STG)          // 24576
#define SCALE_OFF (STAGES * STAGE_BYTES)     // 98304
#define SCALE_PITCH 65                       // padded floats per group row (BN=64)
#define SMEM_TOTAL (SCALE_OFF + 32 * SCALE_PITCH * 4)  // 106624  (x2 CTAs fits 228KB/SM)

// magic-bias int->float exact conversion (|P| < 2^22)
#define MAGIC_I 0x4B400000
#define MAGIC_F 12582912.0f

// ---------------- device scratch ----------------
__device__ int8_t g_W8[(size_t)O_DIM * I_DIM];   // w_int - zero, int8 [O][I]
__device__ int8_t g_X8[(size_t)M_TOT * I_DIM];   // quantized activations [M][I]

// ---------------- asm helpers ----------------
__device__ __forceinline__ uint32_t smem_u32(const void* p) {
    uint32_t a;
    asm("{ .reg .u64 t; cvta.to.shared.u64 t, %1; cvt.u32.u64 %0, t; }" : "=r"(a) : "l"(p));
    return a;
}
#define CP_ASYNC16(saddr, gptr) \
    asm volatile("cp.async.cg.shared.global [%0], [%1], 16;" :: "r"(saddr), "l"(gptr) : "memory")
#define CP_COMMIT() asm volatile("cp.async.commit_group;" ::: "memory")
#define CP_WAIT2()  asm volatile("cp.async.wait_group 2;" ::: "memory")

#define LDSM_X4(r0, r1, r2, r3, addr)                                              \
    asm volatile("ldmatrix.sync.aligned.m8n8.x4.shared.b16 {%0,%1,%2,%3}, [%4];"   \
                 : "=r"(r0), "=r"(r1), "=r"(r2), "=r"(r3) : "r"(addr))

// accumulate form: C==D
#define MMA_S8(c, a, b0_, b1_)                                                     \
    asm volatile("mma.sync.aligned.m16n8k32.row.col.s32.s8.s8.s32 "                \
                 "{%0,%1,%2,%3}, {%4,%5,%6,%7}, {%8,%9}, {%0,%1,%2,%3};"           \
                 : "+r"((c)[0]), "+r"((c)[1]), "+r"((c)[2]), "+r"((c)[3])          \
                 : "r"((a)[0]), "r"((a)[1]), "r"((a)[2]), "r"((a)[3]),             \
                   "r"(b0_), "r"(b1_))

// init form: D = A*B + {mc,mc,mc,mc}  (replaces per-group accumulator resets)
#define MMA_S8_INIT(c, a, b0_, b1_, mc)                                            \
    asm volatile("mma.sync.aligned.m16n8k32.row.col.s32.s8.s8.s32 "                \
                 "{%0,%1,%2,%3}, {%4,%5,%6,%7}, {%8,%9}, {%10,%10,%10,%10};"       \
                 : "=r"((c)[0]), "=r"((c)[1]), "=r"((c)[2]), "=r"((c)[3])          \
                 : "r"((a)[0]), "r"((a)[1]), "r"((a)[2]), "r"((a)[3]),             \
                   "r"(b0_), "r"(b1_), "r"(mc))

// ---------------- kernel 1: fused prep (wpack + quant) ----------------
#define WB (O_DIM * 2048 / 4 / 256)                    // 8192 blocks: weight pack
#define QB ((int)((size_t)M_TOT * I_DIM / 8 / 256))    // 16384 blocks: activation quant

__global__ void prep_kernel(const int* __restrict__ qw, const int* __restrict__ wz,
                            const float* __restrict__ x, const float* __restrict__ as_) {
    if (blockIdx.x < WB) {
        int t = blockIdx.x * blockDim.x + threadIdx.x;
        int o = t >> 9;
        int j = (t & 511) * 4;              // int32 index within row
        int g = j >> 6;                     // group = (2j)/128
        int z = __ldg(&wz[o * 32 + g]);
        int4 q = *reinterpret_cast<const int4*>(qw + (size_t)o * 2048 + j);
        int qs[4] = {q.x, q.y, q.z, q.w};
        uint32_t lo = 0, hi = 0;
#pragma unroll
        for (int r = 0; r < 2; r++) {
            lo |= (uint32_t)(uint8_t)((qs[r] & 15) - z) << (r * 16);
            lo |= (uint32_t)(uint8_t)(((qs[r] >> 4) & 15) - z) << (r * 16 + 8);
            hi |= (uint32_t)(uint8_t)((qs[r + 2] & 15) - z) << (r * 16);
            hi |= (uint32_t)(uint8_t)(((qs[r + 2] >> 4) & 15) - z) << (r * 16 + 8);
        }
        uint2 outv; outv.x = lo; outv.y = hi;
        *reinterpret_cast<uint2*>(&g_W8[(size_t)o * I_DIM + j * 2]) = outv;
    } else {
        int t = (blockIdx.x - WB) * blockDim.x + threadIdx.x;
        size_t e8 = (size_t)t * 8;
        int m = (int)(e8 >> 12);
        float s = __ldg(&as_[m & (S_DIM - 1)]);
        float4 v0 = *reinterpret_cast<const float4*>(x + e8);
        float4 v1 = *reinterpret_cast<const float4*>(x + e8 + 4);
        float vv[8] = {v0.x, v0.y, v0.z, v0.w, v1.x, v1.y, v1.z, v1.w};
        uint32_t lo = 0, hi = 0;
#pragma unroll
        for (int i = 0; i < 4; i++) {
            int n = (int)rintf(vv[i] / s);
            n = max(-127, min(127, n));
            lo |= ((uint32_t)(uint8_t)(int8_t)n) << (i * 8);
        }
#pragma unroll
        for (int i = 0; i < 4; i++) {
            int n = (int)rintf(vv[4 + i] / s);
            n = max(-127, min(127, n));
            hi |= ((uint32_t)(uint8_t)(int8_t)n) << (i * 8);
        }
        uint2 outv; outv.x = lo; outv.y = hi;
        *reinterpret_cast<uint2*>(&g_X8[e8]) = outv;
    }
}

// ---------------- kernel 2: int8 GEMM, induction-pointer loader ----------------
__global__ void __launch_bounds__(256, 2)
gemm_kernel(const float* __restrict__ ws,         // weight_scale [O][32]
            const float* __restrict__ act_scale,  // [2048]
            const float* __restrict__ bias,       // [4096]
            float* __restrict__ out) {            // [M][O]
    extern __shared__ char smem[];
    const uint32_t sbase = smem_u32(smem);
    float* sscale = reinterpret_cast<float*>(smem + SCALE_OFF);

    const int tid  = threadIdx.x;
    const int lane = tid & 31;
    const int wid  = tid >> 5;
    const int wm   = wid & 3;       // 4 warps along M (32 rows each)
    const int wn   = wid >> 2;      // 2 warps along N (32 cols each)
    const int n0   = blockIdx.x * BN;
    const int m0   = blockIdx.y * BM;

    // ---- preload per-column group scales
#pragma unroll
    for (int i = tid; i < BN * 32; i += 256) {
        int nl = i >> 5, g = i & 31;
        sscale[g * SCALE_PITCH + nl] = __ldg(&ws[(size_t)(n0 + nl) * 32 + g]);
    }

    // ---- cp.async induction state: one A pointer, one B pointer, fixed deltas.
    // Thread's 4 A-chunks sit 32*I_DIM apart in gmem and 4096B apart in smem
    // (row += 32 leaves the XOR-swizzle phase unchanged); B-chunks likewise.
    const int lrow = tid >> 3;               // 0..31
    const int lch  = tid & 7;                // 16B chunk
    const uint32_t sw0 = (uint32_t)(lrow * 128 + ((lch ^ (lrow & 7)) << 4));
    const int8_t* pA = g_X8 + (size_t)m0 * I_DIM + (size_t)lrow * I_DIM + lch * 16;
    const int8_t* pB = g_W8 + (size_t)n0 * I_DIM + (size_t)lrow * I_DIM + lch * 16;

    // ---- per-thread ldmatrix address precompute
    const int mi = lane >> 3;          // matrix index 0..3
    const int rr = lane & 7;
    const int c0 = mi >> 1;            // k-half chunk offset
    const int roff = (mi & 1) * 8;
    uint32_t swoff[4];
#pragma unroll
    for (int kk = 0; kk < 4; kk++)
        swoff[kk] = (uint32_t)(((((kk << 1) | c0)) ^ rr) << 4);
    uint32_t rowA128[2], rowB128[2];
#pragma unroll
    for (int mb = 0; mb < 2; mb++) rowA128[mb] = (uint32_t)((wm * 32 + mb * 16 + roff + rr) * 128);
#pragma unroll
    for (int nb = 0; nb < 2; nb++) rowB128[nb] = (uint32_t)((wn * 32 + nb * 16 + roff + rr) * 128);

    // ---- accumulators + double-buffered frags
    int      ai[2][4][4];        // written fresh each stage by MMA_S8_INIT
    float    af[2][4][4];
    uint32_t aF[2][2][4];
    uint32_t bF[2][2][4];
    const int magic_c = MAGIC_I;
#pragma unroll
    for (int mb = 0; mb < 2; mb++)
#pragma unroll
        for (int bb = 0; bb < 4; bb++)
#pragma unroll
            for (int r = 0; r < 4; r++) af[mb][bb][r] = 0.f;

    // ---- stage loader: 6 cp.async from induction pointers, then advance
    auto load_stage = [&](uint32_t slot_base) {
        CP_ASYNC16(slot_base + sw0,                    pA);
        CP_ASYNC16(slot_base + sw0 + 4096,             pA + 32 * I_DIM);
        CP_ASYNC16(slot_base + sw0 + 8192,             pA + 64 * I_DIM);
        CP_ASYNC16(slot_base + sw0 + 12288,            pA + 96 * I_DIM);
        CP_ASYNC16(slot_base + A_STG + sw0,            pB);
        CP_ASYNC16(slot_base + A_STG + sw0 + 4096,     pB + 32 * I_DIM);
        pA += BK;
        pB += BK;
    };

    // fragment loader for one kk chunk into buffer buf
    auto ldsm_kk = [&](uint32_t sA, uint32_t sB, int kk, int buf) {
        const uint32_t so = swoff[kk];
#pragma unroll
        for (int mb = 0; mb < 2; mb++) {
            LDSM_X4(aF[buf][mb][0], aF[buf][mb][1], aF[buf][mb][2], aF[buf][mb][3],
                    sA + rowA128[mb] + so);
        }
#pragma unroll
        for (int nb = 0; nb < 2; nb++) {
            LDSM_X4(bF[buf][nb][0], bF[buf][nb][1], bF[buf][nb][2], bF[buf][nb][3],
                    sB + rowB128[nb] + so);
        }
    };

    const int q2 = (lane & 3) * 2;

    // promote group `g` int sums into float accumulators (read-only on ai)
    auto promote = [&](int g) {
        const float* sp = sscale + g * SCALE_PITCH + wn * 32 + q2;
#pragma unroll
        for (int bb = 0; bb < 4; bb++) {
            const float s0 = sp[bb * 8];
            const float s1 = sp[bb * 8 + 1];
#pragma unroll
            for (int mb = 0; mb < 2; mb++) {
                af[mb][bb][0] = __fmaf_rn(s0, __int_as_float(ai[mb][bb][0]) - MAGIC_F, af[mb][bb][0]);
                af[mb][bb][1] = __fmaf_rn(s1, __int_as_float(ai[mb][bb][1]) - MAGIC_F, af[mb][bb][1]);
                af[mb][bb][2] = __fmaf_rn(s0, __int_as_float(ai[mb][bb][2]) - MAGIC_F, af[mb][bb][2]);
                af[mb][bb][3] = __fmaf_rn(s1, __int_as_float(ai[mb][bb][3]) - MAGIC_F, af[mb][bb][3]);
            }
        }
    };

    // ---- prologue: fill 3 of 4 stages
#pragma unroll
    for (int s = 0; s < STAGES - 1; s++) {
        load_stage(sbase + s * STAGE_BYTES);
        CP_COMMIT();
    }

    for (int ks = 0; ks < NKS; ks++) {
        CP_WAIT2();
        __syncthreads();
        if (ks < NKS - (STAGES - 1)) load_stage(sbase + ((ks + STAGES - 1) & (STAGES - 1)) * STAGE_BYTES);
        CP_COMMIT();

        const uint32_t sA = sbase + (ks & (STAGES - 1)) * STAGE_BYTES;
        const uint32_t sB = sA + A_STG;

        // first fragment load of this stage in flight...
        ldsm_kk(sA, sB, 0, 0);
        // ...promote previous group while LDSM latency drains
        if (ks > 0) promote(ks - 1);

#pragma unroll
        for (int kk = 0; kk < 4; kk++) {
            if (kk < 3) ldsm_kk(sA, sB, kk + 1, (kk + 1) & 1);
            const int buf = kk & 1;
            if (kk == 0) {
#pragma unroll
                for (int mb = 0; mb < 2; mb++)
#pragma unroll
                    for (int bb = 0; bb < 4; bb++) {
                        const int nb = bb >> 1, e = bb & 1;
                        MMA_S8_INIT(ai[mb][bb], aF[buf][mb], bF[buf][nb][e], bF[buf][nb][2 + e], magic_c);
                    }
            } else {
#pragma unroll
                for (int mb = 0; mb < 2; mb++)
#pragma unroll
                    for (int bb = 0; bb < 4; bb++) {
                        const int nb = bb >> 1, e = bb & 1;
                        MMA_S8(ai[mb][bb], aF[buf][mb], bF[buf][nb][e], bF[buf][nb][2 + e]);
                    }
            }
        }
    }
    promote(NKS - 1);

    // ---- epilogue: out = af * act_scale[m] + bias[n]
#pragma unroll
    for (int mb = 0; mb < 2; mb++) {
        const int r0 = m0 + wm * 32 + mb * 16 + (lane >> 2);
        const int r1 = r0 + 8;
        const float sa0 = __ldg(&act_scale[r0 & (S_DIM - 1)]);
        const float sa1 = __ldg(&act_scale[r1 & (S_DIM - 1)]);
#pragma unroll
        for (int bb = 0; bb < 4; bb++) {
            const int n = n0 + wn * 32 + bb * 8 + q2;
            const float2 bv = *reinterpret_cast<const float2*>(bias + n);
            float2 o0, o1;
            o0.x = af[mb][bb][0] * sa0 + bv.x;
            o0.y = af[mb][bb][1] * sa0 + bv.y;
            o1.x = af[mb][bb][2] * sa1 + bv.x;
            o1.y = af[mb][bb][3] * sa1 + bv.y;
            *reinterpret_cast<float2*>(out + (size_t)r0 * O_DIM + n) = o0;
            *reinterpret_cast<float2*>(out + (size_t)r1 * O_DIM + n) = o1;
        }
    }
}

// ---------------- host launcher ----------------
extern "C" void kernel_launch(void* const* d_in, const int* in_sizes, int n_in,
                              void* d_out, int out_size) {
    const float* x    = (const float*)d_in[0];
    const int*   qw   = (const int*)d_in[1];
    const float* as_  = (const float*)d_in[2];
    const float* ws   = (const float*)d_in[3];
    const int*   wz   = (const int*)d_in[4];
    const float* bias = (const float*)d_in[5];
    float* out = (float*)d_out;

    prep_kernel<<<WB + QB, 256>>>(qw, wz, x, as_);

    cudaFuncSetAttribute(gemm_kernel, cudaFuncAttributeMaxDynamicSharedMemorySize,
                         SMEM_TOTAL);
    gemm_kernel<<<dim3(O_DIM / BN, M_TOT / BM), 256, SMEM_TOTAL>>>(ws, as_, bias, out);
}

// round 13
// speedup vs baseline: 1.2395x; 1.1343x over previous
#include <cuda_runtime.h>
#include <cuda_fp16.h>
#include <cstdint>
#include <cstddef>

// ---------------- problem constants ----------------
#define O_DIM 4096
#define I_DIM 4096
#define S_DIM 2048
#define M_TOT 8192            // B*S = 4*2048

// ---------------- GEMM tiling ----------------
#define BM 128
#define BN 64
#define BK 128                // int8 elements per stage = one scale group
#define STAGES 4
#define NKS (I_DIM / BK)      // 32 k-stages
#define A_STG (BM * BK)       // 16384 B
#define B_STG (BN * BK)       // 8192 B
#define STAGE_BYTES (A_STG + B_STG)          // 24576
#define SCALE_OFF (STAGES * STAGE_BYTES)     // 98304
#define SCALE_PITCH 65                       // padded floats per group row (BN=64)
#define SMEM_TOTAL (SCALE_OFF + 32 * SCALE_PITCH * 4)  // 106624  (x2 CTAs fits 228KB/SM)

// magic-bias int->float exact conversion (|P| < 2^22)
#define MAGIC_I 0x4B400000
#define MAGIC_F 12582912.0f

// ---------------- device scratch ----------------
__device__ int8_t g_W8[(size_t)O_DIM * I_DIM];   // w_int - zero, int8 [O][I]
__device__ int8_t g_X8[(size_t)M_TOT * I_DIM];   // quantized activations [M][I]

// ---------------- asm helpers ----------------
__device__ __forceinline__ uint32_t smem_u32(const void* p) {
    uint32_t a;
    asm("{ .reg .u64 t; cvta.to.shared.u64 t, %1; cvt.u32.u64 %0, t; }" : "=r"(a) : "l"(p));
    return a;
}
#define CP_ASYNC16(saddr, gptr) \
    asm volatile("cp.async.cg.shared.global [%0], [%1], 16;" :: "r"(saddr), "l"(gptr) : "memory")
#define CP_COMMIT() asm volatile("cp.async.commit_group;" ::: "memory")
#define CP_WAIT1()  asm volatile("cp.async.wait_group 1;" ::: "memory")

#define LDSM_X4(r0, r1, r2, r3, addr)                                              \
    asm volatile("ldmatrix.sync.aligned.m8n8.x4.shared.b16 {%0,%1,%2,%3}, [%4];"   \
                 : "=r"(r0), "=r"(r1), "=r"(r2), "=r"(r3) : "r"(addr))

// accumulate form: C==D
#define MMA_S8(c, a, b0_, b1_)                                                     \
    asm volatile("mma.sync.aligned.m16n8k32.row.col.s32.s8.s8.s32 "                \
                 "{%0,%1,%2,%3}, {%4,%5,%6,%7}, {%8,%9}, {%0,%1,%2,%3};"           \
                 : "+r"((c)[0]), "+r"((c)[1]), "+r"((c)[2]), "+r"((c)[3])          \
                 : "r"((a)[0]), "r"((a)[1]), "r"((a)[2]), "r"((a)[3]),             \
                   "r"(b0_), "r"(b1_))

// init form: D = A*B + {mc,mc,mc,mc}  (replaces per-group accumulator resets)
#define MMA_S8_INIT(c, a, b0_, b1_, mc)                                            \
    asm volatile("mma.sync.aligned.m16n8k32.row.col.s32.s8.s8.s32 "                \
                 "{%0,%1,%2,%3}, {%4,%5,%6,%7}, {%8,%9}, {%10,%10,%10,%10};"       \
                 : "=r"((c)[0]), "=r"((c)[1]), "=r"((c)[2]), "=r"((c)[3])          \
                 : "r"((a)[0]), "r"((a)[1]), "r"((a)[2]), "r"((a)[3]),             \
                   "r"(b0_), "r"(b1_), "r"(mc))

// ---------------- kernel 1: fused prep (wpack + quant) ----------------
#define WB (O_DIM * 2048 / 4 / 256)                    // 8192 blocks: weight pack
#define QB ((int)((size_t)M_TOT * I_DIM / 8 / 256))    // 16384 blocks: activation quant

__global__ void prep_kernel(const int* __restrict__ qw, const int* __restrict__ wz,
                            const float* __restrict__ x, const float* __restrict__ as_) {
    if (blockIdx.x < WB) {
        int t = blockIdx.x * blockDim.x + threadIdx.x;
        int o = t >> 9;
        int j = (t & 511) * 4;              // int32 index within row
        int g = j >> 6;                     // group = (2j)/128
        int z = __ldg(&wz[o * 32 + g]);
        int4 q = *reinterpret_cast<const int4*>(qw + (size_t)o * 2048 + j);
        int qs[4] = {q.x, q.y, q.z, q.w};
        uint32_t lo = 0, hi = 0;
#pragma unroll
        for (int r = 0; r < 2; r++) {
            lo |= (uint32_t)(uint8_t)((qs[r] & 15) - z) << (r * 16);
            lo |= (uint32_t)(uint8_t)(((qs[r] >> 4) & 15) - z) << (r * 16 + 8);
            hi |= (uint32_t)(uint8_t)((qs[r + 2] & 15) - z) << (r * 16);
            hi |= (uint32_t)(uint8_t)(((qs[r + 2] >> 4) & 15) - z) << (r * 16 + 8);
        }
        uint2 outv; outv.x = lo; outv.y = hi;
        *reinterpret_cast<uint2*>(&g_W8[(size_t)o * I_DIM + j * 2]) = outv;
    } else {
        int t = (blockIdx.x - WB) * blockDim.x + threadIdx.x;
        size_t e8 = (size_t)t * 8;
        int m = (int)(e8 >> 12);
        float s = __ldg(&as_[m & (S_DIM - 1)]);
        float4 v0 = *reinterpret_cast<const float4*>(x + e8);
        float4 v1 = *reinterpret_cast<const float4*>(x + e8 + 4);
        float vv[8] = {v0.x, v0.y, v0.z, v0.w, v1.x, v1.y, v1.z, v1.w};
        uint32_t lo = 0, hi = 0;
#pragma unroll
        for (int i = 0; i < 4; i++) {
            int n = (int)rintf(vv[i] / s);
            n = max(-127, min(127, n));
            lo |= ((uint32_t)(uint8_t)(int8_t)n) << (i * 8);
        }
#pragma unroll
        for (int i = 0; i < 4; i++) {
            int n = (int)rintf(vv[4 + i] / s);
            n = max(-127, min(127, n));
            hi |= ((uint32_t)(uint8_t)(int8_t)n) << (i * 8);
        }
        uint2 outv; outv.x = lo; outv.y = hi;
        *reinterpret_cast<uint2*>(&g_X8[e8]) = outv;
    }
}

// ---------------- kernel 2: int8 GEMM, cross-stage rotated pipeline ----------------
// Invariant: barrier at end of iter ks publishes stage <= ks+2 smem to all warps
// (each iter: exactly one commit_group; wait_group 1 before the barrier).
// Hence a warp may prefetch (ks+1, kk0) fragments during iter ks.
__global__ void __launch_bounds__(256, 2)
gemm_kernel(const float* __restrict__ ws,         // weight_scale [O][32]
            const float* __restrict__ act_scale,  // [2048]
            const float* __restrict__ bias,       // [4096]
            float* __restrict__ out) {            // [M][O]
    extern __shared__ char smem[];
    const uint32_t sbase = smem_u32(smem);
    float* sscale = reinterpret_cast<float*>(smem + SCALE_OFF);

    const int tid  = threadIdx.x;
    const int lane = tid & 31;
    const int wid  = tid >> 5;
    const int wm   = wid & 3;       // 4 warps along M (32 rows each)
    const int wn   = wid >> 2;      // 2 warps along N (32 cols each)
    const int n0   = blockIdx.x * BN;
    const int m0   = blockIdx.y * BM;

    // ---- preload per-column group scales
#pragma unroll
    for (int i = tid; i < BN * 32; i += 256) {
        int nl = i >> 5, g = i & 31;
        sscale[g * SCALE_PITCH + nl] = __ldg(&ws[(size_t)(n0 + nl) * 32 + g]);
    }

    // ---- cp.async induction state
    const int lrow = tid >> 3;               // 0..31
    const int lch  = tid & 7;                // 16B chunk
    const uint32_t sw0 = (uint32_t)(lrow * 128 + ((lch ^ (lrow & 7)) << 4));
    const int8_t* pA = g_X8 + (size_t)m0 * I_DIM + (size_t)lrow * I_DIM + lch * 16;
    const int8_t* pB = g_W8 + (size_t)n0 * I_DIM + (size_t)lrow * I_DIM + lch * 16;

    // ---- per-thread ldmatrix address precompute
    const int mi = lane >> 3;
    const int rr = lane & 7;
    const int c0 = mi >> 1;
    const int roff = (mi & 1) * 8;
    uint32_t swoff[4];
#pragma unroll
    for (int kk = 0; kk < 4; kk++)
        swoff[kk] = (uint32_t)(((((kk << 1) | c0)) ^ rr) << 4);
    uint32_t rowA128[2], rowB128[2];
#pragma unroll
    for (int mb = 0; mb < 2; mb++) rowA128[mb] = (uint32_t)((wm * 32 + mb * 16 + roff + rr) * 128);
#pragma unroll
    for (int nb = 0; nb < 2; nb++) rowB128[nb] = (uint32_t)((wn * 32 + nb * 16 + roff + rr) * 128);

    // ---- accumulators + double-buffered frags
    int      ai[2][4][4];
    float    af[2][4][4];
    uint32_t aF[2][2][4];
    uint32_t bF[2][2][4];
    const int magic_c = MAGIC_I;
#pragma unroll
    for (int mb = 0; mb < 2; mb++)
#pragma unroll
        for (int bb = 0; bb < 4; bb++)
#pragma unroll
            for (int r = 0; r < 4; r++) af[mb][bb][r] = 0.f;

    // ---- stage loader: 6 cp.async from induction pointers, then advance
    auto load_stage = [&](uint32_t slot_base) {
        CP_ASYNC16(slot_base + sw0,                    pA);
        CP_ASYNC16(slot_base + sw0 + 4096,             pA + 32 * I_DIM);
        CP_ASYNC16(slot_base + sw0 + 8192,             pA + 64 * I_DIM);
        CP_ASYNC16(slot_base + sw0 + 12288,            pA + 96 * I_DIM);
        CP_ASYNC16(slot_base + A_STG + sw0,            pB);
        CP_ASYNC16(slot_base + A_STG + sw0 + 4096,     pB + 32 * I_DIM);
        pA += BK;
        pB += BK;
    };

    // fragment loader for one kk chunk of the stage at (sA,sB) into buffer buf
    auto ldsm_kk = [&](uint32_t sA, uint32_t sB, int kk, int buf) {
        const uint32_t so = swoff[kk];
#pragma unroll
        for (int mb = 0; mb < 2; mb++) {
            LDSM_X4(aF[buf][mb][0], aF[buf][mb][1], aF[buf][mb][2], aF[buf][mb][3],
                    sA + rowA128[mb] + so);
        }
#pragma unroll
        for (int nb = 0; nb < 2; nb++) {
            LDSM_X4(bF[buf][nb][0], bF[buf][nb][1], bF[buf][nb][2], bF[buf][nb][3],
                    sB + rowB128[nb] + so);
        }
    };

    const int q2 = (lane & 3) * 2;

    auto promote = [&](int g) {
        const float* sp = sscale + g * SCALE_PITCH + wn * 32 + q2;
#pragma unroll
        for (int bb = 0; bb < 4; bb++) {
            const float s0 = sp[bb * 8];
            const float s1 = sp[bb * 8 + 1];
#pragma unroll
            for (int mb = 0; mb < 2; mb++) {
                af[mb][bb][0] = __fmaf_rn(s0, __int_as_float(ai[mb][bb][0]) - MAGIC_F, af[mb][bb][0]);
                af[mb][bb][1] = __fmaf_rn(s1, __int_as_float(ai[mb][bb][1]) - MAGIC_F, af[mb][bb][1]);
                af[mb][bb][2] = __fmaf_rn(s0, __int_as_float(ai[mb][bb][2]) - MAGIC_F, af[mb][bb][2]);
                af[mb][bb][3] = __fmaf_rn(s1, __int_as_float(ai[mb][bb][3]) - MAGIC_F, af[mb][bb][3]);
            }
        }
    };

    auto mma_block = [&](int buf, bool init) {
        if (init) {
#pragma unroll
            for (int mb = 0; mb < 2; mb++)
#pragma unroll
                for (int bb = 0; bb < 4; bb++) {
                    const int nb = bb >> 1, e = bb & 1;
                    MMA_S8_INIT(ai[mb][bb], aF[buf][mb], bF[buf][nb][e], bF[buf][nb][2 + e], magic_c);
                }
        } else {
#pragma unroll
            for (int mb = 0; mb < 2; mb++)
#pragma unroll
                for (int bb = 0; bb < 4; bb++) {
                    const int nb = bb >> 1, e = bb & 1;
                    MMA_S8(ai[mb][bb], aF[buf][mb], bF[buf][nb][e], bF[buf][nb][2 + e]);
                }
        }
    };

    // ---- prologue: fill stages 0..2, publish stages 0,1, preload (0,kk0)
#pragma unroll
    for (int s = 0; s < STAGES - 1; s++) {
        load_stage(sbase + s * STAGE_BYTES);
        CP_COMMIT();
    }
    CP_WAIT1();          // stages 0,1 complete locally (stage-2 group outstanding)
    __syncthreads();     // publish stages 0,1
    ldsm_kk(sbase, sbase + A_STG, 0, 0);    // (stage 0, kk0) -> buf0

    for (int ks = 0; ks < NKS; ks++) {
        const uint32_t sA  = sbase + (ks & (STAGES - 1)) * STAGE_BYTES;
        const uint32_t sB  = sA + A_STG;

        if (ks > 0) promote(ks - 1);        // overlaps: kk0 frags already resident
        ldsm_kk(sA, sB, 1, 1);
        mma_block(0, true);                 // kk0 (INIT with magic bias)
        ldsm_kk(sA, sB, 2, 0);
        mma_block(1, false);                // kk1
        if (ks + STAGES - 1 < NKS)          // stage ks+3 into slot (ks-1)&3 (read last iter, barrier-protected)
            load_stage(sbase + ((ks + STAGES - 1) & (STAGES - 1)) * STAGE_BYTES);
        CP_COMMIT();                        // exactly one group per iter (may be empty)
        ldsm_kk(sA, sB, 3, 1);
        mma_block(0, false);                // kk2
        if (ks + 1 < NKS) {                 // prefetch (ks+1, kk0); published at prior barrier
            const uint32_t nA = sbase + ((ks + 1) & (STAGES - 1)) * STAGE_BYTES;
            ldsm_kk(nA, nA + A_STG, 0, 0);
        }
        mma_block(1, false);                // kk3
        CP_WAIT1();                         // stage ks+2 complete locally
        __syncthreads();                    // publish stage ks+2; WAR-protect slot (ks)&3
    }
    promote(NKS - 1);

    // ---- epilogue: out = af * act_scale[m] + bias[n]
#pragma unroll
    for (int mb = 0; mb < 2; mb++) {
        const int r0 = m0 + wm * 32 + mb * 16 + (lane >> 2);
        const int r1 = r0 + 8;
        const float sa0 = __ldg(&act_scale[r0 & (S_DIM - 1)]);
        const float sa1 = __ldg(&act_scale[r1 & (S_DIM - 1)]);
#pragma unroll
        for (int bb = 0; bb < 4; bb++) {
            const int n = n0 + wn * 32 + bb * 8 + q2;
            const float2 bv = *reinterpret_cast<const float2*>(bias + n);
            float2 o0, o1;
            o0.x = af[mb][bb][0] * sa0 + bv.x;
            o0.y = af[mb][bb][1] * sa0 + bv.y;
            o1.x = af[mb][bb][2] * sa1 + bv.x;
            o1.y = af[mb][bb][3] * sa1 + bv.y;
            *reinterpret_cast<float2*>(out + (size_t)r0 * O_DIM + n) = o0;
            *reinterpret_cast<float2*>(out + (size_t)r1 * O_DIM + n) = o1;
        }
    }
}

// ---------------- host launcher ----------------
extern "C" void kernel_launch(void* const* d_in, const int* in_sizes, int n_in,
                              void* d_out, int out_size) {
    const float* x    = (const float*)d_in[0];
    const int*   qw   = (const int*)d_in[1];
    const float* as_  = (const float*)d_in[2];
    const float* ws   = (const float*)d_in[3];
    const int*   wz   = (const int*)d_in[4];
    const float* bias = (const float*)d_in[5];
    float* out = (float*)d_out;

    prep_kernel<<<WB + QB, 256>>>(qw, wz, x, as_);

    cudaFuncSetAttribute(gemm_kernel, cudaFuncAttributeMaxDynamicSharedMemorySize,
                         SMEM_TOTAL);
    gemm_kernel<<<dim3(O_DIM / BN, M_TOT / BM), 256, SMEM_TOTAL>>>(ws, as_, bias, out);
}